// round 12
// baseline (speedup 1.0000x reference)
#include <cuda_runtime.h>
#include <math.h>

#define BATCH 8
#define TD 256
#define TE 256
#define DIN 80
#define D 512
#define MEL 80
#define ROWS (BATCH*TD)          // 2048
#define NBLK_LSTM 128

// ----------------------------- scratch (device globals) ---------------------
__device__ __align__(16) float g_h1[ROWS * D];            // attended@W1+b1: [2048][512]
__device__ __align__(16) float g_h2[ROWS * D];            // x@W1+b1      : [2048][512]
__device__ __align__(16) float g_XC[ROWS * 2 * D];        // [x | weighted]: [2048][1024]
__device__ __align__(16) float g_scores[BATCH * TD * TE]; // scores/attn   : [2048][256]
__device__ __align__(16) float g_part[4 * ROWS * D];      // split-K partials
__device__ __align__(16) float g_hbuf[2][BATCH * D];      // double-buffered h
__device__ unsigned g_flags[NBLK_LSTM * 8];               // 32B-padded per-CTA flags

// ----------------------------- helpers --------------------------------------
__device__ __forceinline__ float fast_tanh(float x) {
    float y;
    asm("tanh.approx.f32 %0, %1;" : "=f"(y) : "f"(x));
    return y;
}
__device__ __forceinline__ unsigned ldg_relaxed_u32(const unsigned* p) {
    unsigned v;
    asm volatile("ld.relaxed.gpu.global.u32 %0, [%1];" : "=r"(v) : "l"(p) : "memory");
    return v;
}
__device__ __forceinline__ void stg_relaxed_u32(unsigned* p, unsigned v) {
    asm volatile("st.relaxed.gpu.global.u32 [%0], %1;" :: "l"(p), "r"(v) : "memory");
}
__device__ __forceinline__ void stg_relaxed_f32(float* p, float v) {
    asm volatile("st.relaxed.gpu.global.f32 [%0], %1;" :: "l"(p), "f"(v) : "memory");
}
__device__ __forceinline__ float4 ldg_relaxed_f4(const float4* p) {
    float4 v;
    asm volatile("ld.relaxed.gpu.global.v4.f32 {%0,%1,%2,%3}, [%4];"
                 : "=f"(v.x), "=f"(v.y), "=f"(v.z), "=f"(v.w) : "l"(p) : "memory");
    return v;
}
__device__ __forceinline__ void fence_gpu() {
    asm volatile("fence.acq_rel.gpu;" ::: "memory");
}
__device__ __forceinline__ float sigm_e(float x) { return 1.f / (1.f + __expf(-x)); }
__device__ __forceinline__ float tanh_e(float x) { return 1.f - 2.f / (1.f + __expf(2.f * x)); }
#define DOT4(a,b) ((a).x*(b).x + (a).y*(b).y + (a).z*(b).z + (a).w*(b).w)

// ----------------------------- fast SGEMM: 128x64 tile, 8x4 micro -----------
__global__ void __launch_bounds__(256) sgemm128(
    const float* __restrict__ A, int lda, long sA,
    const float* __restrict__ B, int ldb, long sB,
    float* __restrict__ C, int ldc, long sC,
    int M, int N, int K, const float* __restrict__ bias)
{
    __shared__ float As[16][132];
    __shared__ float Bs[16][64];

    const int tid = threadIdx.x;
    const int tx = tid & 15;
    const int ty = tid >> 4;
    const int m0 = blockIdx.y << 7, n0 = blockIdx.x << 6;
    A += (long)blockIdx.z * sA;
    B += (long)blockIdx.z * sB;
    C += (long)blockIdx.z * sC;

    const int ar = tid >> 2, ac4 = (tid & 3) << 2;
    const int br = tid >> 4, bc4 = (tid & 15) << 2;

    float acc[8][4];
#pragma unroll
    for (int i = 0; i < 8; i++)
#pragma unroll
        for (int j = 0; j < 4; j++) acc[i][j] = 0.f;

    for (int k0 = 0; k0 < K; k0 += 16) {
#pragma unroll
        for (int h = 0; h < 2; h++) {
            int m = ar + (h << 6);
            float4 v = *(const float4*)&A[(long)(m0 + m) * lda + k0 + ac4];
            As[ac4 + 0][m] = v.x;
            As[ac4 + 1][m] = v.y;
            As[ac4 + 2][m] = v.z;
            As[ac4 + 3][m] = v.w;
        }
        float4 bv = make_float4(0.f, 0.f, 0.f, 0.f);
        if (n0 + bc4 + 3 < N) {
            bv = *(const float4*)&B[(long)(k0 + br) * ldb + n0 + bc4];
        } else {
            float* p = (float*)&bv;
#pragma unroll
            for (int c = 0; c < 4; c++)
                if (n0 + bc4 + c < N) p[c] = B[(long)(k0 + br) * ldb + n0 + bc4 + c];
        }
        *(float4*)&Bs[br][bc4] = bv;
        __syncthreads();

#pragma unroll
        for (int k = 0; k < 16; k++) {
            float4 a0 = *(const float4*)&As[k][ty * 8];
            float4 a1 = *(const float4*)&As[k][ty * 8 + 4];
            float4 b4 = *(const float4*)&Bs[k][tx * 4];
            acc[0][0] += a0.x * b4.x; acc[0][1] += a0.x * b4.y; acc[0][2] += a0.x * b4.z; acc[0][3] += a0.x * b4.w;
            acc[1][0] += a0.y * b4.x; acc[1][1] += a0.y * b4.y; acc[1][2] += a0.y * b4.z; acc[1][3] += a0.y * b4.w;
            acc[2][0] += a0.z * b4.x; acc[2][1] += a0.z * b4.y; acc[2][2] += a0.z * b4.z; acc[2][3] += a0.z * b4.w;
            acc[3][0] += a0.w * b4.x; acc[3][1] += a0.w * b4.y; acc[3][2] += a0.w * b4.z; acc[3][3] += a0.w * b4.w;
            acc[4][0] += a1.x * b4.x; acc[4][1] += a1.x * b4.y; acc[4][2] += a1.x * b4.z; acc[4][3] += a1.x * b4.w;
            acc[5][0] += a1.y * b4.x; acc[5][1] += a1.y * b4.y; acc[5][2] += a1.y * b4.z; acc[5][3] += a1.y * b4.w;
            acc[6][0] += a1.z * b4.x; acc[6][1] += a1.z * b4.y; acc[6][2] += a1.z * b4.z; acc[6][3] += a1.z * b4.w;
            acc[7][0] += a1.w * b4.x; acc[7][1] += a1.w * b4.y; acc[7][2] += a1.w * b4.z; acc[7][3] += a1.w * b4.w;
        }
        __syncthreads();
    }

#pragma unroll
    for (int i = 0; i < 8; i++) {
        int m = m0 + ty * 8 + i;
#pragma unroll
        for (int j = 0; j < 4; j++) {
            int n = n0 + tx * 4 + j;
            if (n < N) {
                float v = acc[i][j];
                if (bias) v += bias[n];
                C[(long)m * ldc + n] = v;
            }
        }
    }
}

// ----------------------------- split-K partial reduce ------------------------
__global__ void __launch_bounds__(256) reduce_parts(
    const float* __restrict__ parts, long pstride, int nparts,
    const float* __restrict__ bias, int bmod, float* __restrict__ out, int n)
{
    int i = (blockIdx.x * 256 + threadIdx.x) << 2;
    if (i >= n) return;
    float4 a = *(const float4*)&parts[i];
    for (int p = 1; p < nparts; p++) {
        float4 b = *(const float4*)&parts[(long)p * pstride + i];
        a.x += b.x; a.y += b.y; a.z += b.z; a.w += b.w;
    }
    int bi = i % bmod;
    a.x += bias[bi]; a.y += bias[bi + 1]; a.z += bias[bi + 2]; a.w += bias[bi + 3];
    *(float4*)&out[i] = a;
}

// ----------------------------- persistent LSTM + fused h2 + fused Xg --------
// warp 0: gates (critical). warps 1-4: h2[t-1] = x[t-1]@W1+b1 (sync shadow).
// warps 5-7: Xg ring for step t+2 from inputs@Wk+b (sync shadow).
__global__ void __launch_bounds__(256) lstm_kernel(
    const float* __restrict__ inputs, const float* __restrict__ Wk,
    const float* __restrict__ lstm_b, const float* __restrict__ Wr,
    const float* __restrict__ W1, const float* __restrict__ b1,
    float* __restrict__ dout)
{
    extern __shared__ float s[];
    float* sWr = s;                         // [16 c][512 k]   8192 f
    float* sh = s + 8192;                   // [8 b][512 k]    4096 f
    float* szred = s + 12288;               // [8 b][16 c]      128 f
    float* sW1 = s + 12416;                 // [4 c][512 k]    2048 f
    float* sB1 = s + 14464;                 // [4]
    float* sWk = s + 14468;                 // [16 c][80 k]    1280 f
    float* sBl = s + 15748;                 // [16]
    float* sXg = s + 15764;                 // ring[2][8 b][16 c] 256 f
    const float4* sWrv = (const float4*)sWr;
    float4* shv = (float4*)sh;
    const float4* sW1v = (const float4*)sW1;
    const float4* sWkv = (const float4*)sWk;
    __shared__ unsigned s_base;

    const int tid = threadIdx.x;
    const int hu0 = blockIdx.x << 2;
    const int lane = tid & 31, warp = tid >> 5;
    const int cb = warp & 3, bb = warp >> 2;  // col-block (=gate), batch-block
    const int gb = tid >> 2, gu = tid & 3;    // gate-thread mapping (tid<32)

    // stage Wr slice: sWr[c*512+k] = Wr[k][512*gate + hu0 + u]
    for (int idx = tid; idx < 8192; idx += 256) {
        int c = idx >> 9, k = idx & 511;
        int col = ((c >> 2) << 9) + hu0 + (c & 3);
        sWr[idx] = Wr[k * 2048 + col];
    }
    // stage W1 slice: sW1[c*512+k] = W1[k][hu0 + c]
    for (int idx = tid; idx < 2048; idx += 256) {
        int c = idx >> 9, k = idx & 511;
        sW1[idx] = W1[k * 512 + hu0 + c];
    }
    if (tid < 4) sB1[tid] = b1[hu0 + tid];
    // stage Wk slice: sWk[c*80+k] = Wk[k][512*gate + hu0 + u]
    for (int idx = tid; idx < 1280; idx += 256) {
        int c = idx / 80, k = idx % 80;
        int col = ((c >> 2) << 9) + hu0 + (c & 3);
        sWk[idx] = Wk[k * 2048 + col];
    }
    if (tid < 16) sBl[tid] = lstm_b[((tid >> 2) << 9) + hu0 + (tid & 3)];

    if (tid == 0) s_base = ldg_relaxed_u32(&g_flags[blockIdx.x * 8]);
    if (tid < 32) stg_relaxed_f32(&g_hbuf[0][gb * 512 + hu0 + gu], 0.f);   // h0 = 0
    __syncthreads();

    // prologue: warps 5-7 fill the Xg ring for t=0 and t=1
    if (warp >= 5) {
#pragma unroll
        for (int t2 = 0; t2 < 2; t2++) {
            int p = (warp - 5) * 32 + lane;           // 0..95
#pragma unroll
            for (int rep = 0; rep < 2; rep++) {
                if (rep == 1) { p += 96; if (p >= 128) break; }
                int b = p >> 4, c = p & 15;
                float acc = sBl[c];
                const float4* iv = (const float4*)&inputs[(b * 256 + t2) * 80];
#pragma unroll
                for (int k4 = 0; k4 < 20; k4++) {
                    float4 x = iv[k4];
                    float4 w = sWkv[c * 20 + k4];
                    acc += DOT4(x, w);
                }
                sXg[(t2 & 1) * 128 + p] = acc;
            }
        }
    }
    __syncthreads();
    const unsigned base = s_base;
    if (tid == 0) { fence_gpu(); stg_relaxed_u32(&g_flags[blockIdx.x * 8], base + 1u); }

    float creg = 0.f;

    for (int t = 0; t < TD; t++) {
        const int cur = t & 1, nxt = cur ^ 1;
        const unsigned tgt = base + (unsigned)t + 1u;

        // Xg for this step from the smem ring (produced at step t-2 / prologue)
        float xg0 = 0.f, xg1 = 0.f, xg2 = 0.f, xg3 = 0.f;
        if (tid < 32) {
            const float* xr = &sXg[(t & 1) * 128 + gb * 16 + gu];
            xg0 = xr[0]; xg1 = xr[4]; xg2 = xr[8]; xg3 = xr[12];
        }

        // all-poll-all barrier (R4 champion): warp 0 watches all 128 flags
        if (warp == 0) {
            bool ok;
            do {
                unsigned f0 = ldg_relaxed_u32(&g_flags[(lane) * 8]);
                unsigned f1 = ldg_relaxed_u32(&g_flags[(lane + 32) * 8]);
                unsigned f2 = ldg_relaxed_u32(&g_flags[(lane + 64) * 8]);
                unsigned f3 = ldg_relaxed_u32(&g_flags[(lane + 96) * 8]);
                ok = ((int)(f0 - tgt) >= 0) & ((int)(f1 - tgt) >= 0) &
                     ((int)(f2 - tgt) >= 0) & ((int)(f3 - tgt) >= 0);
            } while (!__all_sync(0xffffffffu, ok));
            fence_gpu();
        }
        __syncthreads();

        // stage h(t) = x[t-1] into SMEM
        const float4* src = (const float4*)g_hbuf[cur];
#pragma unroll
        for (int i = 0; i < 4; i++) shv[tid + (i << 8)] = ldg_relaxed_f4(&src[tid + (i << 8)]);
        __syncthreads();

        // GEMV: warp (cb,bb) computes z[bb*4..+3][cb*4..+3], k lane-vectorized
        float acc[4][4];
#pragma unroll
        for (int i = 0; i < 4; i++)
#pragma unroll
            for (int j = 0; j < 4; j++) acc[i][j] = 0.f;

#pragma unroll
        for (int kk = 0; kk < 4; kk++) {
            const int kv = (kk << 5) + lane;
            float4 h0 = shv[((bb << 2) + 0) * 128 + kv];
            float4 h1 = shv[((bb << 2) + 1) * 128 + kv];
            float4 h2 = shv[((bb << 2) + 2) * 128 + kv];
            float4 h3 = shv[((bb << 2) + 3) * 128 + kv];
            float4 w0 = sWrv[((cb << 2) + 0) * 128 + kv];
            float4 w1 = sWrv[((cb << 2) + 1) * 128 + kv];
            float4 w2 = sWrv[((cb << 2) + 2) * 128 + kv];
            float4 w3 = sWrv[((cb << 2) + 3) * 128 + kv];
            acc[0][0] += DOT4(h0, w0); acc[0][1] += DOT4(h0, w1); acc[0][2] += DOT4(h0, w2); acc[0][3] += DOT4(h0, w3);
            acc[1][0] += DOT4(h1, w0); acc[1][1] += DOT4(h1, w1); acc[1][2] += DOT4(h1, w2); acc[1][3] += DOT4(h1, w3);
            acc[2][0] += DOT4(h2, w0); acc[2][1] += DOT4(h2, w1); acc[2][2] += DOT4(h2, w2); acc[2][3] += DOT4(h2, w3);
            acc[3][0] += DOT4(h3, w0); acc[3][1] += DOT4(h3, w1); acc[3][2] += DOT4(h3, w2); acc[3][3] += DOT4(h3, w3);
        }

        // butterfly reduce over 32 k-lanes
#pragma unroll
        for (int off = 16; off; off >>= 1)
#pragma unroll
            for (int i = 0; i < 4; i++)
#pragma unroll
                for (int j = 0; j < 4; j++)
                    acc[i][j] += __shfl_xor_sync(0xffffffffu, acc[i][j], off);

        if (lane < 16) {
            int i = lane >> 2, j = lane & 3;
            szred[((bb << 2) + i) * 16 + ((cb << 2) + j)] = acc[i][j];
        }
        __syncthreads();

        // warp 0: gates. warps 1-4: fused h2 row t-1. warps 5-7: Xg for t+2.
        if (tid < 32) {
            float zi = szred[gb * 16 + 0 + gu] + xg0;
            float zf = szred[gb * 16 + 4 + gu] + xg1;
            float zg = szred[gb * 16 + 8 + gu] + xg2;
            float zo = szred[gb * 16 + 12 + gu] + xg3;
            float ig = sigm_e(zi);
            float fg = sigm_e(zf);
            float gg = tanh_e(zg);
            float og = sigm_e(zo);
            creg = fg * creg + ig * gg;
            float h = og * tanh_e(creg);
            stg_relaxed_f32(&g_hbuf[nxt][gb * 512 + hu0 + gu], h);
            fence_gpu();
            __syncwarp();
            if (tid == 0) stg_relaxed_u32(&g_flags[blockIdx.x * 8], base + (unsigned)t + 2u);
            // non-critical stores after the flag publish
            g_XC[((gb << 8) + t) * 1024 + hu0 + gu] = h;   // x sequence
            if (t == TD - 1) {
                dout[ROWS * MEL + gb * 512 + hu0 + gu] = h;                 // state_h
                dout[ROWS * MEL + BATCH * D + gb * 512 + hu0 + gu] = creg;  // state_c
            }
        } else if (warp <= 4) {
            if (t > 0) {
                const int w = warp - 1;            // 0..3 -> batches {2w, 2w+1}
                const int trow = t - 1;
                float a0c[4] = {0.f, 0.f, 0.f, 0.f};
                float a1c[4] = {0.f, 0.f, 0.f, 0.f};
#pragma unroll
                for (int j = 0; j < 4; j++) {
                    const int k4 = (j << 5) + lane;
                    float4 hA = shv[((w << 1) + 0) * 128 + k4];
                    float4 hB = shv[((w << 1) + 1) * 128 + k4];
#pragma unroll
                    for (int c = 0; c < 4; c++) {
                        float4 wv = sW1v[c * 128 + k4];
                        a0c[c] += DOT4(hA, wv);
                        a1c[c] += DOT4(hB, wv);
                    }
                }
#pragma unroll
                for (int off = 16; off; off >>= 1)
#pragma unroll
                    for (int c = 0; c < 4; c++) {
                        a0c[c] += __shfl_xor_sync(0xffffffffu, a0c[c], off);
                        a1c[c] += __shfl_xor_sync(0xffffffffu, a1c[c], off);
                    }
#pragma unroll
                for (int c = 0; c < 4; c++) {
                    if (lane == c)
                        g_h2[(((w << 1) << 8) | trow) * 512 + hu0 + c] = a0c[c] + sB1[c];
                    if (lane == 4 + c)
                        g_h2[((((w << 1) + 1) << 8) | trow) * 512 + hu0 + c] = a1c[c] + sB1[c];
                }
            }
        } else if (t < TD - 2) {
            // warps 5-7: produce Xg for step t+2 into ring slot (t&1)
            const int t2 = t + 2;
            int p = (warp - 5) * 32 + lane;
#pragma unroll
            for (int rep = 0; rep < 2; rep++) {
                if (rep == 1) { p += 96; if (p >= 128) break; }
                int b = p >> 4, c = p & 15;
                float a = sBl[c];
                const float4* iv = (const float4*)&inputs[(b * 256 + t2) * 80];
#pragma unroll
                for (int k4 = 0; k4 < 20; k4++) {
                    float4 x = iv[k4];
                    float4 w = sWkv[c * 20 + k4];
                    a += DOT4(x, w);
                }
                sXg[(t & 1) * 128 + p] = a;
            }
        }
    }

    // tail: h2 row TD-1 needs x[TD-1] = h(256), which lives in g_hbuf[0]
    {
        const unsigned tgt = base + (unsigned)TD + 1u;
        if (warp == 0) {
            bool ok;
            do {
                unsigned f0 = ldg_relaxed_u32(&g_flags[(lane) * 8]);
                unsigned f1 = ldg_relaxed_u32(&g_flags[(lane + 32) * 8]);
                unsigned f2 = ldg_relaxed_u32(&g_flags[(lane + 64) * 8]);
                unsigned f3 = ldg_relaxed_u32(&g_flags[(lane + 96) * 8]);
                ok = ((int)(f0 - tgt) >= 0) & ((int)(f1 - tgt) >= 0) &
                     ((int)(f2 - tgt) >= 0) & ((int)(f3 - tgt) >= 0);
            } while (!__all_sync(0xffffffffu, ok));
            fence_gpu();
        }
        __syncthreads();
        const float4* src = (const float4*)g_hbuf[0];
#pragma unroll
        for (int i = 0; i < 4; i++) shv[tid + (i << 8)] = ldg_relaxed_f4(&src[tid + (i << 8)]);
        __syncthreads();
        if (warp >= 1 && warp <= 4) {
            const int w = warp - 1;
            float a0c[4] = {0.f, 0.f, 0.f, 0.f};
            float a1c[4] = {0.f, 0.f, 0.f, 0.f};
#pragma unroll
            for (int j = 0; j < 4; j++) {
                const int k4 = (j << 5) + lane;
                float4 hA = shv[((w << 1) + 0) * 128 + k4];
                float4 hB = shv[((w << 1) + 1) * 128 + k4];
#pragma unroll
                for (int c = 0; c < 4; c++) {
                    float4 wv = sW1v[c * 128 + k4];
                    a0c[c] += DOT4(hA, wv);
                    a1c[c] += DOT4(hB, wv);
                }
            }
#pragma unroll
            for (int off = 16; off; off >>= 1)
#pragma unroll
                for (int c = 0; c < 4; c++) {
                    a0c[c] += __shfl_xor_sync(0xffffffffu, a0c[c], off);
                    a1c[c] += __shfl_xor_sync(0xffffffffu, a1c[c], off);
                }
#pragma unroll
            for (int c = 0; c < 4; c++) {
                if (lane == c)
                    g_h2[(((w << 1) << 8) | (TD - 1)) * 512 + hu0 + c] = a0c[c] + sB1[c];
                if (lane == 4 + c)
                    g_h2[((((w << 1) + 1) << 8) | (TD - 1)) * 512 + hu0 + c] = a1c[c] + sB1[c];
            }
        }
    }
}

// ----------------------------- attention scores -----------------------------
__global__ void __launch_bounds__(256) scores_kernel(const float* __restrict__ W3)
{
    __shared__ float sh1[64 * 65];
    __shared__ float sh2[16 * 64];
    __shared__ float sW3[512];

    const int tid = threadIdx.x;
    const int bz = blockIdx.z, t0 = blockIdx.y << 4, e0 = blockIdx.x << 6;
    const int e = tid & 63, tg = tid >> 6;

    sW3[tid] = W3[tid];
    sW3[tid + 256] = W3[tid + 256];

    float acc[4] = {0.f, 0.f, 0.f, 0.f};

    for (int dc = 0; dc < 512; dc += 64) {
        __syncthreads();
#pragma unroll
        for (int i = 0; i < 4; i++) {
            int q = tid + (i << 8);
            int er = q >> 4, d4 = (q & 15) << 2;
            float4 v = *(const float4*)&g_h1[(long)(bz * 256 + e0 + er) * 512 + dc + d4];
            sh1[(d4 + 0) * 65 + er] = v.x;
            sh1[(d4 + 1) * 65 + er] = v.y;
            sh1[(d4 + 2) * 65 + er] = v.z;
            sh1[(d4 + 3) * 65 + er] = v.w;
        }
        {
            int tt = tid >> 4, d4 = (tid & 15) << 2;
            float4 v = *(const float4*)&g_h2[(long)(bz * 256 + t0 + tt) * 512 + dc + d4];
            *(float4*)&sh2[tt * 64 + d4] = v;
        }
        __syncthreads();

#pragma unroll 8
        for (int d = 0; d < 64; d++) {
            float h1v = sh1[d * 65 + e];
            float w = sW3[dc + d];
#pragma unroll
            for (int i = 0; i < 4; i++) {
                float v = h1v + sh2[(tg * 4 + i) * 64 + d];
                acc[i] += fast_tanh(v) * w;
            }
        }
    }

#pragma unroll
    for (int i = 0; i < 4; i++)
        g_scores[(long)(bz * 256 + t0 + tg * 4 + i) * 256 + e0 + e] = acc[i];
}

// ----------------------------- row softmax (in place) -----------------------
__global__ void __launch_bounds__(256) softmax_kernel()
{
    float* p = g_scores + (long)blockIdx.x * 256;
    const int tid = threadIdx.x;
    const int lane = tid & 31, w = tid >> 5;
    __shared__ float redm[8];
    __shared__ float reds[8];

    float v = p[tid];
    float m = v;
#pragma unroll
    for (int o = 16; o; o >>= 1) m = fmaxf(m, __shfl_xor_sync(0xffffffffu, m, o));
    if (lane == 0) redm[w] = m;
    __syncthreads();
    if (tid < 32) {
        float x = (tid < 8) ? redm[tid] : -1e30f;
#pragma unroll
        for (int o = 4; o; o >>= 1) x = fmaxf(x, __shfl_xor_sync(0xffffffffu, x, o));
        if (tid == 0) redm[0] = x;
    }
    __syncthreads();
    float ev = __expf(v - redm[0]);
    float ssum = ev;
#pragma unroll
    for (int o = 16; o; o >>= 1) ssum += __shfl_xor_sync(0xffffffffu, ssum, o);
    if (lane == 0) reds[w] = ssum;
    __syncthreads();
    if (tid < 32) {
        float x = (tid < 8) ? reds[tid] : 0.f;
#pragma unroll
        for (int o = 4; o; o >>= 1) x += __shfl_xor_sync(0xffffffffu, x, o);
        if (tid == 0) reds[0] = x;
    }
    __syncthreads();
    p[tid] = ev / reds[0];
}

// ----------------------------- launch ---------------------------------------
extern "C" void kernel_launch(void* const* d_in, const int* in_sizes, int n_in,
                              void* d_out, int out_size)
{
    const float* inputs   = (const float*)d_in[0];
    const float* attended = (const float*)d_in[1];
    const float* Wk       = (const float*)d_in[2];
    const float* Wr       = (const float*)d_in[3];
    const float* lstm_b   = (const float*)d_in[4];
    const float* W1       = (const float*)d_in[5];
    const float* b1       = (const float*)d_in[6];
    const float* W3       = (const float*)d_in[7];
    /* b3 (d_in[8]) cancels in softmax */
    const float* Wout     = (const float*)d_in[9];
    const float* bout     = (const float*)d_in[10];
    float* dout = (float*)d_out;

    static float* pH1 = nullptr;
    static float* pH2 = nullptr;
    static float* pXC = nullptr;
    static float* pSc = nullptr;
    static float* pPt = nullptr;
    static cudaStream_t s1 = nullptr;
    static cudaEvent_t evA = nullptr, evB = nullptr;
    static bool attr_done = false;
    if (!pH1) {
        cudaGetSymbolAddress((void**)&pH1, g_h1);
        cudaGetSymbolAddress((void**)&pH2, g_h2);
        cudaGetSymbolAddress((void**)&pXC, g_XC);
        cudaGetSymbolAddress((void**)&pSc, g_scores);
        cudaGetSymbolAddress((void**)&pPt, g_part);
    }
    const int LSTM_SMEM = 16020 * 4;   // 64,080 B
    if (!attr_done) {
        cudaFuncSetAttribute(lstm_kernel, cudaFuncAttributeMaxDynamicSharedMemorySize,
                             LSTM_SMEM);
        cudaStreamCreateWithFlags(&s1, cudaStreamNonBlocking);
        cudaEventCreateWithFlags(&evA, cudaEventDisableTiming);
        cudaEventCreateWithFlags(&evB, cudaEventDisableTiming);
        attr_done = true;
    }
    const long PS = (long)ROWS * D;

    // fork side stream: h1 = attended @ W1 + b1 (independent of LSTM chain)
    cudaEventRecord(evA, 0);
    cudaStreamWaitEvent(s1, evA, 0);
    sgemm128<<<dim3(8, 16, 2), 256, 0, s1>>>(attended, D, 256, W1, D, 256L * D,
                                             pPt + 2 * PS, D, PS, ROWS, D, 256, nullptr);
    reduce_parts<<<PS / 1024, 256, 0, s1>>>(pPt + 2 * PS, PS, 2, b1, D, pH1, (int)PS);
    cudaEventRecord(evB, s1);

    // main stream: LSTM (Xg + h2 folded in) -> (join h1) scores -> softmax -> ...
    lstm_kernel<<<NBLK_LSTM, 256, LSTM_SMEM>>>(inputs, Wk, lstm_b, Wr, W1, b1, dout);

    cudaStreamWaitEvent(0, evB, 0);   // join h1 before scores
    scores_kernel<<<dim3(4, 16, 8), 256>>>(W3);
    softmax_kernel<<<ROWS, 256>>>();
    sgemm128<<<dim3(8, 2, 8), 256>>>(pSc, TE, (long)TD * TE,
                                     attended, D, (long)TE * D,
                                     pXC + D, 2 * D, (long)TD * 2 * D,
                                     TD, D, TE, nullptr);
    {
        const long OS = (long)ROWS * MEL;
        sgemm128<<<dim3(2, 16, 4), 256>>>(pXC, 2 * D, 256, Wout, MEL, 256L * MEL,
                                          pPt, MEL, OS, ROWS, MEL, 256, nullptr);
        reduce_parts<<<(unsigned)(OS / 1024), 256>>>(pPt, OS, 4, bout, MEL, dout, (int)OS);
    }
}

// round 13
// speedup vs baseline: 1.1560x; 1.1560x over previous
#include <cuda_runtime.h>
#include <math.h>

#define BATCH 8
#define TD 256
#define TE 256
#define DIN 80
#define D 512
#define MEL 80
#define ROWS (BATCH*TD)          // 2048
#define NBLK_LSTM 128

// ----------------------------- scratch (device globals) ---------------------
__device__ __align__(16) float g_Xg[ROWS * 4 * D];        // inputs@Wk + b : [2048][2048]
__device__ __align__(16) float g_h1[ROWS * D];            // attended@W1+b1: [2048][512]
__device__ __align__(16) float g_h2[ROWS * D];            // x@W1+b1      : [2048][512]
__device__ __align__(16) float g_XC[ROWS * 2 * D];        // [x | weighted]: [2048][1024]
__device__ __align__(16) float g_scores[BATCH * TD * TE]; // scores/attn   : [2048][256]
__device__ __align__(16) float g_part[4 * ROWS * D];      // split-K partials
__device__ __align__(16) float g_hbuf[2][BATCH * D];      // double-buffered h
__device__ unsigned g_flags[NBLK_LSTM * 8];               // 32B-padded per-CTA flags

// ----------------------------- helpers --------------------------------------
__device__ __forceinline__ float fast_tanh(float x) {
    float y;
    asm("tanh.approx.f32 %0, %1;" : "=f"(y) : "f"(x));
    return y;
}
__device__ __forceinline__ unsigned ldg_relaxed_u32(const unsigned* p) {
    unsigned v;
    asm volatile("ld.relaxed.gpu.global.u32 %0, [%1];" : "=r"(v) : "l"(p) : "memory");
    return v;
}
__device__ __forceinline__ void stg_relaxed_u32(unsigned* p, unsigned v) {
    asm volatile("st.relaxed.gpu.global.u32 [%0], %1;" :: "l"(p), "r"(v) : "memory");
}
__device__ __forceinline__ void stg_relaxed_f32(float* p, float v) {
    asm volatile("st.relaxed.gpu.global.f32 [%0], %1;" :: "l"(p), "f"(v) : "memory");
}
__device__ __forceinline__ float4 ldg_relaxed_f4(const float4* p) {
    float4 v;
    asm volatile("ld.relaxed.gpu.global.v4.f32 {%0,%1,%2,%3}, [%4];"
                 : "=f"(v.x), "=f"(v.y), "=f"(v.z), "=f"(v.w) : "l"(p) : "memory");
    return v;
}
__device__ __forceinline__ void fence_gpu() {
    asm volatile("fence.acq_rel.gpu;" ::: "memory");
}
__device__ __forceinline__ float sigm_e(float x) { return 1.f / (1.f + __expf(-x)); }
__device__ __forceinline__ float tanh_e(float x) { return 1.f - 2.f / (1.f + __expf(2.f * x)); }
#define DOT4(a,b) ((a).x*(b).x + (a).y*(b).y + (a).z*(b).z + (a).w*(b).w)

// ----------------------------- fast SGEMM: 128x64 tile, 8x4 micro -----------
__global__ void __launch_bounds__(256) sgemm128(
    const float* __restrict__ A, int lda, long sA,
    const float* __restrict__ B, int ldb, long sB,
    float* __restrict__ C, int ldc, long sC,
    int M, int N, int K, const float* __restrict__ bias)
{
    __shared__ float As[16][132];
    __shared__ float Bs[16][64];

    const int tid = threadIdx.x;
    const int tx = tid & 15;
    const int ty = tid >> 4;
    const int m0 = blockIdx.y << 7, n0 = blockIdx.x << 6;
    A += (long)blockIdx.z * sA;
    B += (long)blockIdx.z * sB;
    C += (long)blockIdx.z * sC;

    const int ar = tid >> 2, ac4 = (tid & 3) << 2;
    const int br = tid >> 4, bc4 = (tid & 15) << 2;

    float acc[8][4];
#pragma unroll
    for (int i = 0; i < 8; i++)
#pragma unroll
        for (int j = 0; j < 4; j++) acc[i][j] = 0.f;

    for (int k0 = 0; k0 < K; k0 += 16) {
#pragma unroll
        for (int h = 0; h < 2; h++) {
            int m = ar + (h << 6);
            float4 v = *(const float4*)&A[(long)(m0 + m) * lda + k0 + ac4];
            As[ac4 + 0][m] = v.x;
            As[ac4 + 1][m] = v.y;
            As[ac4 + 2][m] = v.z;
            As[ac4 + 3][m] = v.w;
        }
        float4 bv = make_float4(0.f, 0.f, 0.f, 0.f);
        if (n0 + bc4 + 3 < N) {
            bv = *(const float4*)&B[(long)(k0 + br) * ldb + n0 + bc4];
        } else {
            float* p = (float*)&bv;
#pragma unroll
            for (int c = 0; c < 4; c++)
                if (n0 + bc4 + c < N) p[c] = B[(long)(k0 + br) * ldb + n0 + bc4 + c];
        }
        *(float4*)&Bs[br][bc4] = bv;
        __syncthreads();

#pragma unroll
        for (int k = 0; k < 16; k++) {
            float4 a0 = *(const float4*)&As[k][ty * 8];
            float4 a1 = *(const float4*)&As[k][ty * 8 + 4];
            float4 b4 = *(const float4*)&Bs[k][tx * 4];
            acc[0][0] += a0.x * b4.x; acc[0][1] += a0.x * b4.y; acc[0][2] += a0.x * b4.z; acc[0][3] += a0.x * b4.w;
            acc[1][0] += a0.y * b4.x; acc[1][1] += a0.y * b4.y; acc[1][2] += a0.y * b4.z; acc[1][3] += a0.y * b4.w;
            acc[2][0] += a0.z * b4.x; acc[2][1] += a0.z * b4.y; acc[2][2] += a0.z * b4.z; acc[2][3] += a0.z * b4.w;
            acc[3][0] += a0.w * b4.x; acc[3][1] += a0.w * b4.y; acc[3][2] += a0.w * b4.z; acc[3][3] += a0.w * b4.w;
            acc[4][0] += a1.x * b4.x; acc[4][1] += a1.x * b4.y; acc[4][2] += a1.x * b4.z; acc[4][3] += a1.x * b4.w;
            acc[5][0] += a1.y * b4.x; acc[5][1] += a1.y * b4.y; acc[5][2] += a1.y * b4.z; acc[5][3] += a1.y * b4.w;
            acc[6][0] += a1.z * b4.x; acc[6][1] += a1.z * b4.y; acc[6][2] += a1.z * b4.z; acc[6][3] += a1.z * b4.w;
            acc[7][0] += a1.w * b4.x; acc[7][1] += a1.w * b4.y; acc[7][2] += a1.w * b4.z; acc[7][3] += a1.w * b4.w;
        }
        __syncthreads();
    }

#pragma unroll
    for (int i = 0; i < 8; i++) {
        int m = m0 + ty * 8 + i;
#pragma unroll
        for (int j = 0; j < 4; j++) {
            int n = n0 + tx * 4 + j;
            if (n < N) {
                float v = acc[i][j];
                if (bias) v += bias[n];
                C[(long)m * ldc + n] = v;
            }
        }
    }
}

// ----------------------------- split-K partial reduce ------------------------
__global__ void __launch_bounds__(256) reduce_parts(
    const float* __restrict__ parts, long pstride, int nparts,
    const float* __restrict__ bias, int bmod, float* __restrict__ out, int n)
{
    int i = (blockIdx.x * 256 + threadIdx.x) << 2;
    if (i >= n) return;
    float4 a = *(const float4*)&parts[i];
    for (int p = 1; p < nparts; p++) {
        float4 b = *(const float4*)&parts[(long)p * pstride + i];
        a.x += b.x; a.y += b.y; a.z += b.z; a.w += b.w;
    }
    int bi = i % bmod;
    a.x += bias[bi]; a.y += bias[bi + 1]; a.z += bias[bi + 2]; a.w += bias[bi + 3];
    *(float4*)&out[i] = a;
}

// ----------------------------- persistent LSTM + fused h2 -------------------
// R11 champion + store-reorder: flag published immediately after h store,
// g_XC/dout stores moved after the publish (consumed only at kernel boundary).
__global__ void __launch_bounds__(256) lstm_kernel(
    const float* __restrict__ Wr, const float* __restrict__ W1,
    const float* __restrict__ b1, float* __restrict__ dout)
{
    extern __shared__ float s[];
    float* sWr = s;                         // [16 cols][512 k]   8192 f
    float* sh = s + 8192;                   // [8 b][512 k]       4096 f
    float* szred = s + 12288;               // [8 b][16 c]         128 f
    float* sW1 = s + 12416;                 // [4 c][512 k]       2048 f
    float* sB1 = s + 14464;                 // [4]
    const float4* sWrv = (const float4*)sWr;
    float4* shv = (float4*)sh;
    const float4* sW1v = (const float4*)sW1;
    __shared__ unsigned s_base;

    const int tid = threadIdx.x;
    const int hu0 = blockIdx.x << 2;
    const int lane = tid & 31, warp = tid >> 5;
    const int cb = warp & 3, bb = warp >> 2;  // col-block (=gate), batch-block
    const int gb = tid >> 2, gu = tid & 3;    // gate-thread mapping (tid<32)

    // stage Wr slice: sWr[c*512+k] = Wr[k][512*gate + hu0 + u]
    for (int idx = tid; idx < 8192; idx += 256) {
        int c = idx >> 9, k = idx & 511;
        int col = ((c >> 2) << 9) + hu0 + (c & 3);
        sWr[idx] = Wr[k * 2048 + col];
    }
    // stage W1 slice: sW1[c*512+k] = W1[k][hu0 + c]
    for (int idx = tid; idx < 2048; idx += 256) {
        int c = idx >> 9, k = idx & 511;
        sW1[idx] = W1[k * 512 + hu0 + c];
    }
    if (tid < 4) sB1[tid] = b1[hu0 + tid];

    if (tid == 0) s_base = ldg_relaxed_u32(&g_flags[blockIdx.x * 8]);
    if (tid < 32) stg_relaxed_f32(&g_hbuf[0][gb * 512 + hu0 + gu], 0.f);   // h0 = 0
    __syncthreads();
    const unsigned base = s_base;
    if (tid == 0) { fence_gpu(); stg_relaxed_u32(&g_flags[blockIdx.x * 8], base + 1u); }

    float creg = 0.f;

    for (int t = 0; t < TD; t++) {
        const int cur = t & 1, nxt = cur ^ 1;
        const unsigned tgt = base + (unsigned)t + 1u;

        // prefetch Xg for this step (overlaps the wait)
        float xg0 = 0.f, xg1 = 0.f, xg2 = 0.f, xg3 = 0.f;
        if (tid < 32) {
            const float* xr = &g_Xg[((gb << 8) + t) * 2048 + hu0 + gu];
            xg0 = xr[0]; xg1 = xr[512]; xg2 = xr[1024]; xg3 = xr[1536];
        }

        // all-poll-all barrier (R4 champion): warp 0 watches all 128 flags
        if (warp == 0) {
            bool ok;
            do {
                unsigned f0 = ldg_relaxed_u32(&g_flags[(lane) * 8]);
                unsigned f1 = ldg_relaxed_u32(&g_flags[(lane + 32) * 8]);
                unsigned f2 = ldg_relaxed_u32(&g_flags[(lane + 64) * 8]);
                unsigned f3 = ldg_relaxed_u32(&g_flags[(lane + 96) * 8]);
                ok = ((int)(f0 - tgt) >= 0) & ((int)(f1 - tgt) >= 0) &
                     ((int)(f2 - tgt) >= 0) & ((int)(f3 - tgt) >= 0);
            } while (!__all_sync(0xffffffffu, ok));
            fence_gpu();
        }
        __syncthreads();

        // stage h(t) = x[t-1] into SMEM
        const float4* src = (const float4*)g_hbuf[cur];
#pragma unroll
        for (int i = 0; i < 4; i++) shv[tid + (i << 8)] = ldg_relaxed_f4(&src[tid + (i << 8)]);
        __syncthreads();

        // GEMV: warp (cb,bb) computes z[bb*4..+3][cb*4..+3], k lane-vectorized
        float acc[4][4];
#pragma unroll
        for (int i = 0; i < 4; i++)
#pragma unroll
            for (int j = 0; j < 4; j++) acc[i][j] = 0.f;

#pragma unroll
        for (int kk = 0; kk < 4; kk++) {
            const int kv = (kk << 5) + lane;
            float4 h0 = shv[((bb << 2) + 0) * 128 + kv];
            float4 h1 = shv[((bb << 2) + 1) * 128 + kv];
            float4 h2 = shv[((bb << 2) + 2) * 128 + kv];
            float4 h3 = shv[((bb << 2) + 3) * 128 + kv];
            float4 w0 = sWrv[((cb << 2) + 0) * 128 + kv];
            float4 w1 = sWrv[((cb << 2) + 1) * 128 + kv];
            float4 w2 = sWrv[((cb << 2) + 2) * 128 + kv];
            float4 w3 = sWrv[((cb << 2) + 3) * 128 + kv];
            acc[0][0] += DOT4(h0, w0); acc[0][1] += DOT4(h0, w1); acc[0][2] += DOT4(h0, w2); acc[0][3] += DOT4(h0, w3);
            acc[1][0] += DOT4(h1, w0); acc[1][1] += DOT4(h1, w1); acc[1][2] += DOT4(h1, w2); acc[1][3] += DOT4(h1, w3);
            acc[2][0] += DOT4(h2, w0); acc[2][1] += DOT4(h2, w1); acc[2][2] += DOT4(h2, w2); acc[2][3] += DOT4(h2, w3);
            acc[3][0] += DOT4(h3, w0); acc[3][1] += DOT4(h3, w1); acc[3][2] += DOT4(h3, w2); acc[3][3] += DOT4(h3, w3);
        }

        // butterfly reduce over 32 k-lanes
#pragma unroll
        for (int off = 16; off; off >>= 1)
#pragma unroll
            for (int i = 0; i < 4; i++)
#pragma unroll
                for (int j = 0; j < 4; j++)
                    acc[i][j] += __shfl_xor_sync(0xffffffffu, acc[i][j], off);

        if (lane < 16) {
            int i = lane >> 2, j = lane & 3;
            szred[((bb << 2) + i) * 16 + ((cb << 2) + j)] = acc[i][j];
        }
        __syncthreads();

        // warp 0: gates (critical path). warps 1-4: fused h2 row t-1.
        if (tid < 32) {
            float zi = szred[gb * 16 + 0 + gu] + xg0;
            float zf = szred[gb * 16 + 4 + gu] + xg1;
            float zg = szred[gb * 16 + 8 + gu] + xg2;
            float zo = szred[gb * 16 + 12 + gu] + xg3;
            float ig = sigm_e(zi);
            float fg = sigm_e(zf);
            float gg = tanh_e(zg);
            float og = sigm_e(zo);
            creg = fg * creg + ig * gg;
            float h = og * tanh_e(creg);
            stg_relaxed_f32(&g_hbuf[nxt][gb * 512 + hu0 + gu], h);
            fence_gpu();
            __syncwarp();
            if (tid == 0) stg_relaxed_u32(&g_flags[blockIdx.x * 8], base + (unsigned)t + 2u);
            // non-critical stores after the flag publish
            g_XC[((gb << 8) + t) * 1024 + hu0 + gu] = h;   // x sequence
            if (t == TD - 1) {
                dout[ROWS * MEL + gb * 512 + hu0 + gu] = h;                 // state_h
                dout[ROWS * MEL + BATCH * D + gb * 512 + hu0 + gu] = creg;  // state_c
            }
        } else if (warp <= 4 && t > 0) {
            const int w = warp - 1;            // 0..3 -> batches {2w, 2w+1}
            const int trow = t - 1;
            float a0c[4] = {0.f, 0.f, 0.f, 0.f};
            float a1c[4] = {0.f, 0.f, 0.f, 0.f};
#pragma unroll
            for (int j = 0; j < 4; j++) {
                const int k4 = (j << 5) + lane;
                float4 hA = shv[((w << 1) + 0) * 128 + k4];
                float4 hB = shv[((w << 1) + 1) * 128 + k4];
#pragma unroll
                for (int c = 0; c < 4; c++) {
                    float4 wv = sW1v[c * 128 + k4];
                    a0c[c] += DOT4(hA, wv);
                    a1c[c] += DOT4(hB, wv);
                }
            }
#pragma unroll
            for (int off = 16; off; off >>= 1)
#pragma unroll
                for (int c = 0; c < 4; c++) {
                    a0c[c] += __shfl_xor_sync(0xffffffffu, a0c[c], off);
                    a1c[c] += __shfl_xor_sync(0xffffffffu, a1c[c], off);
                }
#pragma unroll
            for (int c = 0; c < 4; c++) {
                if (lane == c)
                    g_h2[(((w << 1) << 8) | trow) * 512 + hu0 + c] = a0c[c] + sB1[c];
                if (lane == 4 + c)
                    g_h2[((((w << 1) + 1) << 8) | trow) * 512 + hu0 + c] = a1c[c] + sB1[c];
            }
        }
    }

    // tail: h2 row TD-1 needs x[TD-1] = h(256), which lives in g_hbuf[0]
    {
        const unsigned tgt = base + (unsigned)TD + 1u;
        if (warp == 0) {
            bool ok;
            do {
                unsigned f0 = ldg_relaxed_u32(&g_flags[(lane) * 8]);
                unsigned f1 = ldg_relaxed_u32(&g_flags[(lane + 32) * 8]);
                unsigned f2 = ldg_relaxed_u32(&g_flags[(lane + 64) * 8]);
                unsigned f3 = ldg_relaxed_u32(&g_flags[(lane + 96) * 8]);
                ok = ((int)(f0 - tgt) >= 0) & ((int)(f1 - tgt) >= 0) &
                     ((int)(f2 - tgt) >= 0) & ((int)(f3 - tgt) >= 0);
            } while (!__all_sync(0xffffffffu, ok));
            fence_gpu();
        }
        __syncthreads();
        const float4* src = (const float4*)g_hbuf[0];
#pragma unroll
        for (int i = 0; i < 4; i++) shv[tid + (i << 8)] = ldg_relaxed_f4(&src[tid + (i << 8)]);
        __syncthreads();
        if (warp >= 1 && warp <= 4) {
            const int w = warp - 1;
            float a0c[4] = {0.f, 0.f, 0.f, 0.f};
            float a1c[4] = {0.f, 0.f, 0.f, 0.f};
#pragma unroll
            for (int j = 0; j < 4; j++) {
                const int k4 = (j << 5) + lane;
                float4 hA = shv[((w << 1) + 0) * 128 + k4];
                float4 hB = shv[((w << 1) + 1) * 128 + k4];
#pragma unroll
                for (int c = 0; c < 4; c++) {
                    float4 wv = sW1v[c * 128 + k4];
                    a0c[c] += DOT4(hA, wv);
                    a1c[c] += DOT4(hB, wv);
                }
            }
#pragma unroll
            for (int off = 16; off; off >>= 1)
#pragma unroll
                for (int c = 0; c < 4; c++) {
                    a0c[c] += __shfl_xor_sync(0xffffffffu, a0c[c], off);
                    a1c[c] += __shfl_xor_sync(0xffffffffu, a1c[c], off);
                }
#pragma unroll
            for (int c = 0; c < 4; c++) {
                if (lane == c)
                    g_h2[(((w << 1) << 8) | (TD - 1)) * 512 + hu0 + c] = a0c[c] + sB1[c];
                if (lane == 4 + c)
                    g_h2[((((w << 1) + 1) << 8) | (TD - 1)) * 512 + hu0 + c] = a1c[c] + sB1[c];
            }
        }
    }
}

// ----------------------------- attention scores -----------------------------
__global__ void __launch_bounds__(256) scores_kernel(const float* __restrict__ W3)
{
    __shared__ float sh1[64 * 65];
    __shared__ float sh2[16 * 64];
    __shared__ float sW3[512];

    const int tid = threadIdx.x;
    const int bz = blockIdx.z, t0 = blockIdx.y << 4, e0 = blockIdx.x << 6;
    const int e = tid & 63, tg = tid >> 6;

    sW3[tid] = W3[tid];
    sW3[tid + 256] = W3[tid + 256];

    float acc[4] = {0.f, 0.f, 0.f, 0.f};

    for (int dc = 0; dc < 512; dc += 64) {
        __syncthreads();
#pragma unroll
        for (int i = 0; i < 4; i++) {
            int q = tid + (i << 8);
            int er = q >> 4, d4 = (q & 15) << 2;
            float4 v = *(const float4*)&g_h1[(long)(bz * 256 + e0 + er) * 512 + dc + d4];
            sh1[(d4 + 0) * 65 + er] = v.x;
            sh1[(d4 + 1) * 65 + er] = v.y;
            sh1[(d4 + 2) * 65 + er] = v.z;
            sh1[(d4 + 3) * 65 + er] = v.w;
        }
        {
            int tt = tid >> 4, d4 = (tid & 15) << 2;
            float4 v = *(const float4*)&g_h2[(long)(bz * 256 + t0 + tt) * 512 + dc + d4];
            *(float4*)&sh2[tt * 64 + d4] = v;
        }
        __syncthreads();

#pragma unroll 8
        for (int d = 0; d < 64; d++) {
            float h1v = sh1[d * 65 + e];
            float w = sW3[dc + d];
#pragma unroll
            for (int i = 0; i < 4; i++) {
                float v = h1v + sh2[(tg * 4 + i) * 64 + d];
                acc[i] += fast_tanh(v) * w;
            }
        }
    }

#pragma unroll
    for (int i = 0; i < 4; i++)
        g_scores[(long)(bz * 256 + t0 + tg * 4 + i) * 256 + e0 + e] = acc[i];
}

// ----------------------------- row softmax (in place) -----------------------
__global__ void __launch_bounds__(256) softmax_kernel()
{
    float* p = g_scores + (long)blockIdx.x * 256;
    const int tid = threadIdx.x;
    const int lane = tid & 31, w = tid >> 5;
    __shared__ float redm[8];
    __shared__ float reds[8];

    float v = p[tid];
    float m = v;
#pragma unroll
    for (int o = 16; o; o >>= 1) m = fmaxf(m, __shfl_xor_sync(0xffffffffu, m, o));
    if (lane == 0) redm[w] = m;
    __syncthreads();
    if (tid < 32) {
        float x = (tid < 8) ? redm[tid] : -1e30f;
#pragma unroll
        for (int o = 4; o; o >>= 1) x = fmaxf(x, __shfl_xor_sync(0xffffffffu, x, o));
        if (tid == 0) redm[0] = x;
    }
    __syncthreads();
    float ev = __expf(v - redm[0]);
    float ssum = ev;
#pragma unroll
    for (int o = 16; o; o >>= 1) ssum += __shfl_xor_sync(0xffffffffu, ssum, o);
    if (lane == 0) reds[w] = ssum;
    __syncthreads();
    if (tid < 32) {
        float x = (tid < 8) ? reds[tid] : 0.f;
#pragma unroll
        for (int o = 4; o; o >>= 1) x += __shfl_xor_sync(0xffffffffu, x, o);
        if (tid == 0) reds[0] = x;
    }
    __syncthreads();
    p[tid] = ev / reds[0];
}

// ----------------------------- launch ---------------------------------------
extern "C" void kernel_launch(void* const* d_in, const int* in_sizes, int n_in,
                              void* d_out, int out_size)
{
    const float* inputs   = (const float*)d_in[0];
    const float* attended = (const float*)d_in[1];
    const float* Wk       = (const float*)d_in[2];
    const float* Wr       = (const float*)d_in[3];
    const float* lstm_b   = (const float*)d_in[4];
    const float* W1       = (const float*)d_in[5];
    const float* b1       = (const float*)d_in[6];
    const float* W3       = (const float*)d_in[7];
    /* b3 (d_in[8]) cancels in softmax */
    const float* Wout     = (const float*)d_in[9];
    const float* bout     = (const float*)d_in[10];
    float* dout = (float*)d_out;

    static float* pXg = nullptr;
    static float* pH1 = nullptr;
    static float* pH2 = nullptr;
    static float* pXC = nullptr;
    static float* pSc = nullptr;
    static float* pPt = nullptr;
    static cudaStream_t s1 = nullptr;
    static cudaEvent_t evA = nullptr, evB = nullptr;
    static bool attr_done = false;
    if (!pXg) {
        cudaGetSymbolAddress((void**)&pXg, g_Xg);
        cudaGetSymbolAddress((void**)&pH1, g_h1);
        cudaGetSymbolAddress((void**)&pH2, g_h2);
        cudaGetSymbolAddress((void**)&pXC, g_XC);
        cudaGetSymbolAddress((void**)&pSc, g_scores);
        cudaGetSymbolAddress((void**)&pPt, g_part);
    }
    const int LSTM_SMEM = 14468 * 4;   // 57,872 B
    if (!attr_done) {
        cudaFuncSetAttribute(lstm_kernel, cudaFuncAttributeMaxDynamicSharedMemorySize,
                             LSTM_SMEM);
        cudaStreamCreateWithFlags(&s1, cudaStreamNonBlocking);
        cudaEventCreateWithFlags(&evA, cudaEventDisableTiming);
        cudaEventCreateWithFlags(&evB, cudaEventDisableTiming);
        attr_done = true;
    }
    const long PS = (long)ROWS * D;

    // fork side stream: h1 = attended @ W1 + b1 (independent of LSTM chain)
    cudaEventRecord(evA, 0);
    cudaStreamWaitEvent(s1, evA, 0);
    sgemm128<<<dim3(8, 16, 2), 256, 0, s1>>>(attended, D, 256, W1, D, 256L * D,
                                             pPt + 2 * PS, D, PS, ROWS, D, 256, nullptr);
    reduce_parts<<<PS / 1024, 256, 0, s1>>>(pPt + 2 * PS, PS, 2, b1, D, pH1, (int)PS);
    cudaEventRecord(evB, s1);

    // main stream: Xg -> LSTM(+h2 fold) -> (join h1) scores -> softmax -> weighted -> out
    sgemm128<<<dim3(32, 16, 1), 256>>>(inputs, DIN, 0, Wk, 4 * D, 0,
                                       pXg, 4 * D, 0, ROWS, 4 * D, DIN, lstm_b);
    lstm_kernel<<<NBLK_LSTM, 256, LSTM_SMEM>>>(Wr, W1, b1, dout);

    cudaStreamWaitEvent(0, evB, 0);   // join h1 before scores
    scores_kernel<<<dim3(4, 16, 8), 256>>>(W3);
    softmax_kernel<<<ROWS, 256>>>();
    sgemm128<<<dim3(8, 2, 8), 256>>>(pSc, TE, (long)TD * TE,
                                     attended, D, (long)TE * D,
                                     pXC + D, 2 * D, (long)TD * 2 * D,
                                     TD, D, TE, nullptr);
    {
        const long OS = (long)ROWS * MEL;
        sgemm128<<<dim3(2, 16, 4), 256>>>(pXC, 2 * D, 256, Wout, MEL, 256L * MEL,
                                          pPt, MEL, OS, ROWS, MEL, 256, nullptr);
        reduce_parts<<<(unsigned)(OS / 1024), 256>>>(pPt, OS, 4, bout, MEL, dout, (int)OS);
    }
}

// round 14
// speedup vs baseline: 1.3699x; 1.1850x over previous
#include <cuda_runtime.h>
#include <math.h>

#define BATCH 8
#define TD 256
#define TE 256
#define DIN 80
#define D 512
#define MEL 80
#define ROWS (BATCH*TD)          // 2048
#define NBLK_LSTM 128

// ----------------------------- scratch (device globals) ---------------------
__device__ __align__(16) float g_Xg[ROWS * 4 * D];        // inputs@Wk + b : [2048][2048]
__device__ __align__(16) float g_h1[ROWS * D];            // attended@W1+b1: [2048][512]
__device__ __align__(16) float g_h2[ROWS * D];            // x@W1+b1      : [2048][512]
__device__ __align__(16) float g_XC[ROWS * 2 * D];        // [x | weighted]: [2048][1024]
__device__ __align__(16) float g_scores[BATCH * TD * TE]; // scores/attn   : [2048][256]
__device__ __align__(16) float g_part[4 * ROWS * D];      // split-K partials
__device__ __align__(16) float g_hbuf[2][BATCH * D];      // double-buffered h
__device__ unsigned g_flags[NBLK_LSTM * 8];               // 32B-padded per-CTA flags

// ----------------------------- helpers --------------------------------------
__device__ __forceinline__ float fast_tanh(float x) {
    float y;
    asm("tanh.approx.f32 %0, %1;" : "=f"(y) : "f"(x));
    return y;
}
__device__ __forceinline__ unsigned ldg_relaxed_u32(const unsigned* p) {
    unsigned v;
    asm volatile("ld.relaxed.gpu.global.u32 %0, [%1];" : "=r"(v) : "l"(p) : "memory");
    return v;
}
__device__ __forceinline__ void stg_relaxed_u32(unsigned* p, unsigned v) {
    asm volatile("st.relaxed.gpu.global.u32 [%0], %1;" :: "l"(p), "r"(v) : "memory");
}
__device__ __forceinline__ void stg_relaxed_f32(float* p, float v) {
    asm volatile("st.relaxed.gpu.global.f32 [%0], %1;" :: "l"(p), "f"(v) : "memory");
}
__device__ __forceinline__ float4 ldg_relaxed_f4(const float4* p) {
    float4 v;
    asm volatile("ld.relaxed.gpu.global.v4.f32 {%0,%1,%2,%3}, [%4];"
                 : "=f"(v.x), "=f"(v.y), "=f"(v.z), "=f"(v.w) : "l"(p) : "memory");
    return v;
}
__device__ __forceinline__ void fence_gpu() {
    asm volatile("fence.acq_rel.gpu;" ::: "memory");
}
__device__ __forceinline__ float sigm_e(float x) { return 1.f / (1.f + __expf(-x)); }
__device__ __forceinline__ float tanh_e(float x) { return 1.f - 2.f / (1.f + __expf(2.f * x)); }
#define DOT4(a,b) ((a).x*(b).x + (a).y*(b).y + (a).z*(b).z + (a).w*(b).w)

// ----------------------------- fast SGEMM: 128x64 tile, 8x4 micro -----------
__global__ void __launch_bounds__(256) sgemm128(
    const float* __restrict__ A, int lda, long sA,
    const float* __restrict__ B, int ldb, long sB,
    float* __restrict__ C, int ldc, long sC,
    int M, int N, int K, const float* __restrict__ bias)
{
    __shared__ float As[16][132];
    __shared__ float Bs[16][64];

    const int tid = threadIdx.x;
    const int tx = tid & 15;
    const int ty = tid >> 4;
    const int m0 = blockIdx.y << 7, n0 = blockIdx.x << 6;
    A += (long)blockIdx.z * sA;
    B += (long)blockIdx.z * sB;
    C += (long)blockIdx.z * sC;

    const int ar = tid >> 2, ac4 = (tid & 3) << 2;
    const int br = tid >> 4, bc4 = (tid & 15) << 2;

    float acc[8][4];
#pragma unroll
    for (int i = 0; i < 8; i++)
#pragma unroll
        for (int j = 0; j < 4; j++) acc[i][j] = 0.f;

    for (int k0 = 0; k0 < K; k0 += 16) {
#pragma unroll
        for (int h = 0; h < 2; h++) {
            int m = ar + (h << 6);
            float4 v = *(const float4*)&A[(long)(m0 + m) * lda + k0 + ac4];
            As[ac4 + 0][m] = v.x;
            As[ac4 + 1][m] = v.y;
            As[ac4 + 2][m] = v.z;
            As[ac4 + 3][m] = v.w;
        }
        float4 bv = make_float4(0.f, 0.f, 0.f, 0.f);
        if (n0 + bc4 + 3 < N) {
            bv = *(const float4*)&B[(long)(k0 + br) * ldb + n0 + bc4];
        } else {
            float* p = (float*)&bv;
#pragma unroll
            for (int c = 0; c < 4; c++)
                if (n0 + bc4 + c < N) p[c] = B[(long)(k0 + br) * ldb + n0 + bc4 + c];
        }
        *(float4*)&Bs[br][bc4] = bv;
        __syncthreads();

#pragma unroll
        for (int k = 0; k < 16; k++) {
            float4 a0 = *(const float4*)&As[k][ty * 8];
            float4 a1 = *(const float4*)&As[k][ty * 8 + 4];
            float4 b4 = *(const float4*)&Bs[k][tx * 4];
            acc[0][0] += a0.x * b4.x; acc[0][1] += a0.x * b4.y; acc[0][2] += a0.x * b4.z; acc[0][3] += a0.x * b4.w;
            acc[1][0] += a0.y * b4.x; acc[1][1] += a0.y * b4.y; acc[1][2] += a0.y * b4.z; acc[1][3] += a0.y * b4.w;
            acc[2][0] += a0.z * b4.x; acc[2][1] += a0.z * b4.y; acc[2][2] += a0.z * b4.z; acc[2][3] += a0.z * b4.w;
            acc[3][0] += a0.w * b4.x; acc[3][1] += a0.w * b4.y; acc[3][2] += a0.w * b4.z; acc[3][3] += a0.w * b4.w;
            acc[4][0] += a1.x * b4.x; acc[4][1] += a1.x * b4.y; acc[4][2] += a1.x * b4.z; acc[4][3] += a1.x * b4.w;
            acc[5][0] += a1.y * b4.x; acc[5][1] += a1.y * b4.y; acc[5][2] += a1.y * b4.z; acc[5][3] += a1.y * b4.w;
            acc[6][0] += a1.z * b4.x; acc[6][1] += a1.z * b4.y; acc[6][2] += a1.z * b4.z; acc[6][3] += a1.z * b4.w;
            acc[7][0] += a1.w * b4.x; acc[7][1] += a1.w * b4.y; acc[7][2] += a1.w * b4.z; acc[7][3] += a1.w * b4.w;
        }
        __syncthreads();
    }

#pragma unroll
    for (int i = 0; i < 8; i++) {
        int m = m0 + ty * 8 + i;
#pragma unroll
        for (int j = 0; j < 4; j++) {
            int n = n0 + tx * 4 + j;
            if (n < N) {
                float v = acc[i][j];
                if (bias) v += bias[n];
                C[(long)m * ldc + n] = v;
            }
        }
    }
}

// ----------------------------- split-K partial reduce ------------------------
__global__ void __launch_bounds__(256) reduce_parts(
    const float* __restrict__ parts, long pstride, int nparts,
    const float* __restrict__ bias, int bmod, float* __restrict__ out, int n)
{
    int i = (blockIdx.x * 256 + threadIdx.x) << 2;
    if (i >= n) return;
    float4 a = *(const float4*)&parts[i];
    for (int p = 1; p < nparts; p++) {
        float4 b = *(const float4*)&parts[(long)p * pstride + i];
        a.x += b.x; a.y += b.y; a.z += b.z; a.w += b.w;
    }
    int bi = i % bmod;
    a.x += bias[bi]; a.y += bias[bi + 1]; a.z += bias[bi + 2]; a.w += bias[bi + 3];
    *(float4*)&out[i] = a;
}

// ----------------------------- persistent LSTM + fused h2 (R11 exact) -------
__global__ void __launch_bounds__(256) lstm_kernel(
    const float* __restrict__ Wr, const float* __restrict__ W1,
    const float* __restrict__ b1, float* __restrict__ dout)
{
    extern __shared__ float s[];
    float* sWr = s;                         // [16 cols][512 k]   8192 f
    float* sh = s + 8192;                   // [8 b][512 k]       4096 f
    float* szred = s + 12288;               // [8 b][16 c]         128 f
    float* sW1 = s + 12416;                 // [4 c][512 k]       2048 f
    float* sB1 = s + 14464;                 // [4]
    const float4* sWrv = (const float4*)sWr;
    float4* shv = (float4*)sh;
    const float4* sW1v = (const float4*)sW1;
    __shared__ unsigned s_base;

    const int tid = threadIdx.x;
    const int hu0 = blockIdx.x << 2;
    const int lane = tid & 31, warp = tid >> 5;
    const int cb = warp & 3, bb = warp >> 2;  // col-block (=gate), batch-block
    const int gb = tid >> 2, gu = tid & 3;    // gate-thread mapping (tid<32)

    // stage Wr slice: sWr[c*512+k] = Wr[k][512*gate + hu0 + u]
    for (int idx = tid; idx < 8192; idx += 256) {
        int c = idx >> 9, k = idx & 511;
        int col = ((c >> 2) << 9) + hu0 + (c & 3);
        sWr[idx] = Wr[k * 2048 + col];
    }
    // stage W1 slice: sW1[c*512+k] = W1[k][hu0 + c]
    for (int idx = tid; idx < 2048; idx += 256) {
        int c = idx >> 9, k = idx & 511;
        sW1[idx] = W1[k * 512 + hu0 + c];
    }
    if (tid < 4) sB1[tid] = b1[hu0 + tid];

    if (tid == 0) s_base = ldg_relaxed_u32(&g_flags[blockIdx.x * 8]);
    if (tid < 32) stg_relaxed_f32(&g_hbuf[0][gb * 512 + hu0 + gu], 0.f);   // h0 = 0
    __syncthreads();
    const unsigned base = s_base;
    if (tid == 0) { fence_gpu(); stg_relaxed_u32(&g_flags[blockIdx.x * 8], base + 1u); }

    float creg = 0.f;

    for (int t = 0; t < TD; t++) {
        const int cur = t & 1, nxt = cur ^ 1;
        const unsigned tgt = base + (unsigned)t + 1u;

        // prefetch Xg for this step (overlaps the wait)
        float xg0 = 0.f, xg1 = 0.f, xg2 = 0.f, xg3 = 0.f;
        if (tid < 32) {
            const float* xr = &g_Xg[((gb << 8) + t) * 2048 + hu0 + gu];
            xg0 = xr[0]; xg1 = xr[512]; xg2 = xr[1024]; xg3 = xr[1536];
        }

        // all-poll-all barrier (R4 champion): warp 0 watches all 128 flags
        if (warp == 0) {
            bool ok;
            do {
                unsigned f0 = ldg_relaxed_u32(&g_flags[(lane) * 8]);
                unsigned f1 = ldg_relaxed_u32(&g_flags[(lane + 32) * 8]);
                unsigned f2 = ldg_relaxed_u32(&g_flags[(lane + 64) * 8]);
                unsigned f3 = ldg_relaxed_u32(&g_flags[(lane + 96) * 8]);
                ok = ((int)(f0 - tgt) >= 0) & ((int)(f1 - tgt) >= 0) &
                     ((int)(f2 - tgt) >= 0) & ((int)(f3 - tgt) >= 0);
            } while (!__all_sync(0xffffffffu, ok));
            fence_gpu();
        }
        __syncthreads();

        // stage h(t) = x[t-1] into SMEM
        const float4* src = (const float4*)g_hbuf[cur];
#pragma unroll
        for (int i = 0; i < 4; i++) shv[tid + (i << 8)] = ldg_relaxed_f4(&src[tid + (i << 8)]);
        __syncthreads();

        // GEMV: warp (cb,bb) computes z[bb*4..+3][cb*4..+3], k lane-vectorized
        float acc[4][4];
#pragma unroll
        for (int i = 0; i < 4; i++)
#pragma unroll
            for (int j = 0; j < 4; j++) acc[i][j] = 0.f;

#pragma unroll
        for (int kk = 0; kk < 4; kk++) {
            const int kv = (kk << 5) + lane;
            float4 h0 = shv[((bb << 2) + 0) * 128 + kv];
            float4 h1 = shv[((bb << 2) + 1) * 128 + kv];
            float4 h2 = shv[((bb << 2) + 2) * 128 + kv];
            float4 h3 = shv[((bb << 2) + 3) * 128 + kv];
            float4 w0 = sWrv[((cb << 2) + 0) * 128 + kv];
            float4 w1 = sWrv[((cb << 2) + 1) * 128 + kv];
            float4 w2 = sWrv[((cb << 2) + 2) * 128 + kv];
            float4 w3 = sWrv[((cb << 2) + 3) * 128 + kv];
            acc[0][0] += DOT4(h0, w0); acc[0][1] += DOT4(h0, w1); acc[0][2] += DOT4(h0, w2); acc[0][3] += DOT4(h0, w3);
            acc[1][0] += DOT4(h1, w0); acc[1][1] += DOT4(h1, w1); acc[1][2] += DOT4(h1, w2); acc[1][3] += DOT4(h1, w3);
            acc[2][0] += DOT4(h2, w0); acc[2][1] += DOT4(h2, w1); acc[2][2] += DOT4(h2, w2); acc[2][3] += DOT4(h2, w3);
            acc[3][0] += DOT4(h3, w0); acc[3][1] += DOT4(h3, w1); acc[3][2] += DOT4(h3, w2); acc[3][3] += DOT4(h3, w3);
        }

        // butterfly reduce over 32 k-lanes
#pragma unroll
        for (int off = 16; off; off >>= 1)
#pragma unroll
            for (int i = 0; i < 4; i++)
#pragma unroll
                for (int j = 0; j < 4; j++)
                    acc[i][j] += __shfl_xor_sync(0xffffffffu, acc[i][j], off);

        if (lane < 16) {
            int i = lane >> 2, j = lane & 3;
            szred[((bb << 2) + i) * 16 + ((cb << 2) + j)] = acc[i][j];
        }
        __syncthreads();

        // warp 0: gates (critical path). warps 1-4: fused h2 row t-1.
        if (tid < 32) {
            float zi = szred[gb * 16 + 0 + gu] + xg0;
            float zf = szred[gb * 16 + 4 + gu] + xg1;
            float zg = szred[gb * 16 + 8 + gu] + xg2;
            float zo = szred[gb * 16 + 12 + gu] + xg3;
            float ig = sigm_e(zi);
            float fg = sigm_e(zf);
            float gg = tanh_e(zg);
            float og = sigm_e(zo);
            creg = fg * creg + ig * gg;
            float h = og * tanh_e(creg);
            stg_relaxed_f32(&g_hbuf[nxt][gb * 512 + hu0 + gu], h);
            g_XC[((gb << 8) + t) * 1024 + hu0 + gu] = h;   // x sequence
            if (t == TD - 1) {
                dout[ROWS * MEL + gb * 512 + hu0 + gu] = h;                 // state_h
                dout[ROWS * MEL + BATCH * D + gb * 512 + hu0 + gu] = creg;  // state_c
            }
            fence_gpu();
            __syncwarp();
            if (tid == 0) stg_relaxed_u32(&g_flags[blockIdx.x * 8], base + (unsigned)t + 2u);
        } else if (warp <= 4 && t > 0) {
            const int w = warp - 1;            // 0..3 -> batches {2w, 2w+1}
            const int trow = t - 1;
            float a0c[4] = {0.f, 0.f, 0.f, 0.f};
            float a1c[4] = {0.f, 0.f, 0.f, 0.f};
#pragma unroll
            for (int j = 0; j < 4; j++) {
                const int k4 = (j << 5) + lane;
                float4 hA = shv[((w << 1) + 0) * 128 + k4];
                float4 hB = shv[((w << 1) + 1) * 128 + k4];
#pragma unroll
                for (int c = 0; c < 4; c++) {
                    float4 wv = sW1v[c * 128 + k4];
                    a0c[c] += DOT4(hA, wv);
                    a1c[c] += DOT4(hB, wv);
                }
            }
#pragma unroll
            for (int off = 16; off; off >>= 1)
#pragma unroll
                for (int c = 0; c < 4; c++) {
                    a0c[c] += __shfl_xor_sync(0xffffffffu, a0c[c], off);
                    a1c[c] += __shfl_xor_sync(0xffffffffu, a1c[c], off);
                }
#pragma unroll
            for (int c = 0; c < 4; c++) {
                if (lane == c)
                    g_h2[(((w << 1) << 8) | trow) * 512 + hu0 + c] = a0c[c] + sB1[c];
                if (lane == 4 + c)
                    g_h2[((((w << 1) + 1) << 8) | trow) * 512 + hu0 + c] = a1c[c] + sB1[c];
            }
        }
    }

    // tail: h2 row TD-1 needs x[TD-1] = h(256), which lives in g_hbuf[0]
    {
        const unsigned tgt = base + (unsigned)TD + 1u;
        if (warp == 0) {
            bool ok;
            do {
                unsigned f0 = ldg_relaxed_u32(&g_flags[(lane) * 8]);
                unsigned f1 = ldg_relaxed_u32(&g_flags[(lane + 32) * 8]);
                unsigned f2 = ldg_relaxed_u32(&g_flags[(lane + 64) * 8]);
                unsigned f3 = ldg_relaxed_u32(&g_flags[(lane + 96) * 8]);
                ok = ((int)(f0 - tgt) >= 0) & ((int)(f1 - tgt) >= 0) &
                     ((int)(f2 - tgt) >= 0) & ((int)(f3 - tgt) >= 0);
            } while (!__all_sync(0xffffffffu, ok));
            fence_gpu();
        }
        __syncthreads();
        const float4* src = (const float4*)g_hbuf[0];
#pragma unroll
        for (int i = 0; i < 4; i++) shv[tid + (i << 8)] = ldg_relaxed_f4(&src[tid + (i << 8)]);
        __syncthreads();
        if (warp >= 1 && warp <= 4) {
            const int w = warp - 1;
            float a0c[4] = {0.f, 0.f, 0.f, 0.f};
            float a1c[4] = {0.f, 0.f, 0.f, 0.f};
#pragma unroll
            for (int j = 0; j < 4; j++) {
                const int k4 = (j << 5) + lane;
                float4 hA = shv[((w << 1) + 0) * 128 + k4];
                float4 hB = shv[((w << 1) + 1) * 128 + k4];
#pragma unroll
                for (int c = 0; c < 4; c++) {
                    float4 wv = sW1v[c * 128 + k4];
                    a0c[c] += DOT4(hA, wv);
                    a1c[c] += DOT4(hB, wv);
                }
            }
#pragma unroll
            for (int off = 16; off; off >>= 1)
#pragma unroll
                for (int c = 0; c < 4; c++) {
                    a0c[c] += __shfl_xor_sync(0xffffffffu, a0c[c], off);
                    a1c[c] += __shfl_xor_sync(0xffffffffu, a1c[c], off);
                }
#pragma unroll
            for (int c = 0; c < 4; c++) {
                if (lane == c)
                    g_h2[(((w << 1) << 8) | (TD - 1)) * 512 + hu0 + c] = a0c[c] + sB1[c];
                if (lane == 4 + c)
                    g_h2[((((w << 1) + 1) << 8) | (TD - 1)) * 512 + hu0 + c] = a1c[c] + sB1[c];
            }
        }
    }
}

// ----------------------------- attention scores -----------------------------
__global__ void __launch_bounds__(256) scores_kernel(const float* __restrict__ W3)
{
    __shared__ float sh1[64 * 65];
    __shared__ float sh2[16 * 64];
    __shared__ float sW3[512];

    const int tid = threadIdx.x;
    const int bz = blockIdx.z, t0 = blockIdx.y << 4, e0 = blockIdx.x << 6;
    const int e = tid & 63, tg = tid >> 6;

    sW3[tid] = W3[tid];
    sW3[tid + 256] = W3[tid + 256];

    float acc[4] = {0.f, 0.f, 0.f, 0.f};

    for (int dc = 0; dc < 512; dc += 64) {
        __syncthreads();
#pragma unroll
        for (int i = 0; i < 4; i++) {
            int q = tid + (i << 8);
            int er = q >> 4, d4 = (q & 15) << 2;
            float4 v = *(const float4*)&g_h1[(long)(bz * 256 + e0 + er) * 512 + dc + d4];
            sh1[(d4 + 0) * 65 + er] = v.x;
            sh1[(d4 + 1) * 65 + er] = v.y;
            sh1[(d4 + 2) * 65 + er] = v.z;
            sh1[(d4 + 3) * 65 + er] = v.w;
        }
        {
            int tt = tid >> 4, d4 = (tid & 15) << 2;
            float4 v = *(const float4*)&g_h2[(long)(bz * 256 + t0 + tt) * 512 + dc + d4];
            *(float4*)&sh2[tt * 64 + d4] = v;
        }
        __syncthreads();

#pragma unroll 8
        for (int d = 0; d < 64; d++) {
            float h1v = sh1[d * 65 + e];
            float w = sW3[dc + d];
#pragma unroll
            for (int i = 0; i < 4; i++) {
                float v = h1v + sh2[(tg * 4 + i) * 64 + d];
                acc[i] += fast_tanh(v) * w;
            }
        }
    }

#pragma unroll
    for (int i = 0; i < 4; i++)
        g_scores[(long)(bz * 256 + t0 + tg * 4 + i) * 256 + e0 + e] = acc[i];
}

// ----------------------------- row softmax (in place) -----------------------
__global__ void __launch_bounds__(256) softmax_kernel()
{
    float* p = g_scores + (long)blockIdx.x * 256;
    const int tid = threadIdx.x;
    const int lane = tid & 31, w = tid >> 5;
    __shared__ float redm[8];
    __shared__ float reds[8];

    float v = p[tid];
    float m = v;
#pragma unroll
    for (int o = 16; o; o >>= 1) m = fmaxf(m, __shfl_xor_sync(0xffffffffu, m, o));
    if (lane == 0) redm[w] = m;
    __syncthreads();
    if (tid < 32) {
        float x = (tid < 8) ? redm[tid] : -1e30f;
#pragma unroll
        for (int o = 4; o; o >>= 1) x = fmaxf(x, __shfl_xor_sync(0xffffffffu, x, o));
        if (tid == 0) redm[0] = x;
    }
    __syncthreads();
    float ev = __expf(v - redm[0]);
    float ssum = ev;
#pragma unroll
    for (int o = 16; o; o >>= 1) ssum += __shfl_xor_sync(0xffffffffu, ssum, o);
    if (lane == 0) reds[w] = ssum;
    __syncthreads();
    if (tid < 32) {
        float x = (tid < 8) ? reds[tid] : 0.f;
#pragma unroll
        for (int o = 4; o; o >>= 1) x += __shfl_xor_sync(0xffffffffu, x, o);
        if (tid == 0) reds[0] = x;
    }
    __syncthreads();
    p[tid] = ev / reds[0];
}

// ----------------------------- launch ---------------------------------------
extern "C" void kernel_launch(void* const* d_in, const int* in_sizes, int n_in,
                              void* d_out, int out_size)
{
    const float* inputs   = (const float*)d_in[0];
    const float* attended = (const float*)d_in[1];
    const float* Wk       = (const float*)d_in[2];
    const float* Wr       = (const float*)d_in[3];
    const float* lstm_b   = (const float*)d_in[4];
    const float* W1       = (const float*)d_in[5];
    const float* b1       = (const float*)d_in[6];
    const float* W3       = (const float*)d_in[7];
    /* b3 (d_in[8]) cancels in softmax */
    const float* Wout     = (const float*)d_in[9];
    const float* bout     = (const float*)d_in[10];
    float* dout = (float*)d_out;

    static float* pXg = nullptr;
    static float* pH1 = nullptr;
    static float* pH2 = nullptr;
    static float* pXC = nullptr;
    static float* pSc = nullptr;
    static float* pPt = nullptr;
    static cudaStream_t s1 = nullptr, s2 = nullptr;
    static cudaEvent_t evA = nullptr, evB = nullptr, evC = nullptr, evD = nullptr;
    static bool attr_done = false;
    if (!pXg) {
        cudaGetSymbolAddress((void**)&pXg, g_Xg);
        cudaGetSymbolAddress((void**)&pH1, g_h1);
        cudaGetSymbolAddress((void**)&pH2, g_h2);
        cudaGetSymbolAddress((void**)&pXC, g_XC);
        cudaGetSymbolAddress((void**)&pSc, g_scores);
        cudaGetSymbolAddress((void**)&pPt, g_part);
    }
    const int LSTM_SMEM = 14468 * 4;   // 57,872 B
    if (!attr_done) {
        cudaFuncSetAttribute(lstm_kernel, cudaFuncAttributeMaxDynamicSharedMemorySize,
                             LSTM_SMEM);
        cudaStreamCreateWithFlags(&s1, cudaStreamNonBlocking);
        cudaStreamCreateWithFlags(&s2, cudaStreamNonBlocking);
        cudaEventCreateWithFlags(&evA, cudaEventDisableTiming);
        cudaEventCreateWithFlags(&evB, cudaEventDisableTiming);
        cudaEventCreateWithFlags(&evC, cudaEventDisableTiming);
        cudaEventCreateWithFlags(&evD, cudaEventDisableTiming);
        attr_done = true;
    }
    const long PS = (long)ROWS * D;      // 1M floats
    const long OS = (long)ROWS * MEL;    // 163,840 floats

    // fork side stream s1: h1 = attended @ W1 + b1 (independent of LSTM chain)
    cudaEventRecord(evA, 0);
    cudaStreamWaitEvent(s1, evA, 0);
    sgemm128<<<dim3(8, 16, 2), 256, 0, s1>>>(attended, D, 256, W1, D, 256L * D,
                                             pPt + 2 * PS, D, PS, ROWS, D, 256, nullptr);
    reduce_parts<<<PS / 1024, 256, 0, s1>>>(pPt + 2 * PS, PS, 2, b1, D, pH1, (int)PS);
    cudaEventRecord(evB, s1);

    // main stream: Xg -> LSTM(+h2 fold)
    sgemm128<<<dim3(32, 16, 1), 256>>>(inputs, DIN, 0, Wk, 4 * D, 0,
                                       pXg, 4 * D, 0, ROWS, 4 * D, DIN, lstm_b);
    lstm_kernel<<<NBLK_LSTM, 256, LSTM_SMEM>>>(Wr, W1, b1, dout);
    cudaEventRecord(evC, 0);

    // side stream s2: x-half of output GEMM (depends only on LSTM's x) —
    // runs concurrent with scores/softmax. parts 0,1 of 4.
    cudaStreamWaitEvent(s2, evC, 0);
    sgemm128<<<dim3(2, 16, 2), 256, 0, s2>>>(pXC, 2 * D, 256, Wout, MEL, 256L * MEL,
                                             pPt, MEL, OS, ROWS, MEL, 256, nullptr);
    cudaEventRecord(evD, s2);

    // main stream: (join h1) scores -> softmax -> weighted
    cudaStreamWaitEvent(0, evB, 0);
    scores_kernel<<<dim3(4, 16, 8), 256>>>(W3);
    softmax_kernel<<<ROWS, 256>>>();
    sgemm128<<<dim3(8, 2, 8), 256>>>(pSc, TE, (long)TD * TE,
                                     attended, D, (long)TE * D,
                                     pXC + D, 2 * D, (long)TD * 2 * D,
                                     TD, D, TE, nullptr);
    // weighted-half of output GEMM: parts 2,3 of 4
    sgemm128<<<dim3(2, 16, 2), 256>>>(pXC + D, 2 * D, 256,
                                      Wout + 512L * MEL, MEL, 256L * MEL,
                                      pPt + 2 * OS, MEL, OS, ROWS, MEL, 256, nullptr);
    // join x-half, reduce all 4 parts + bias -> dout
    cudaStreamWaitEvent(0, evD, 0);
    reduce_parts<<<(unsigned)(OS / 1024), 256>>>(pPt, OS, 4, bout, MEL, dout, (int)OS);
}

// round 15
// speedup vs baseline: 1.4215x; 1.0377x over previous
#include <cuda_runtime.h>
#include <math.h>

#define BATCH 8
#define TD 256
#define TE 256
#define DIN 80
#define D 512
#define MEL 80
#define ROWS (BATCH*TD)          // 2048
#define NBLK_LSTM 128

// ----------------------------- scratch (device globals) ---------------------
__device__ __align__(16) float g_Xg[ROWS * 4 * D];        // inputs@Wk + b : [2048][2048]
__device__ __align__(16) float g_h1[ROWS * D];            // attended@W1+b1: [2048][512]
__device__ __align__(16) float g_h2[ROWS * D];            // x@W1+b1      : [2048][512]
__device__ __align__(16) float g_XC[ROWS * 2 * D];        // [x | weighted]: [2048][1024]
__device__ __align__(16) float g_scores[BATCH * TD * TE]; // scores/attn   : [2048][256]
__device__ __align__(16) float g_part[4 * ROWS * D];      // split-K partials
__device__ __align__(16) float g_hbuf[2][BATCH * D];      // double-buffered h
__device__ unsigned g_flags[NBLK_LSTM * 8];               // 32B-padded per-CTA flags

// ----------------------------- helpers --------------------------------------
__device__ __forceinline__ float fast_tanh(float x) {
    float y;
    asm("tanh.approx.f32 %0, %1;" : "=f"(y) : "f"(x));
    return y;
}
__device__ __forceinline__ unsigned ldg_relaxed_u32(const unsigned* p) {
    unsigned v;
    asm volatile("ld.relaxed.gpu.global.u32 %0, [%1];" : "=r"(v) : "l"(p) : "memory");
    return v;
}
__device__ __forceinline__ void stg_relaxed_u32(unsigned* p, unsigned v) {
    asm volatile("st.relaxed.gpu.global.u32 [%0], %1;" :: "l"(p), "r"(v) : "memory");
}
__device__ __forceinline__ void stg_relaxed_f32(float* p, float v) {
    asm volatile("st.relaxed.gpu.global.f32 [%0], %1;" :: "l"(p), "f"(v) : "memory");
}
__device__ __forceinline__ float4 ldg_relaxed_f4(const float4* p) {
    float4 v;
    asm volatile("ld.relaxed.gpu.global.v4.f32 {%0,%1,%2,%3}, [%4];"
                 : "=f"(v.x), "=f"(v.y), "=f"(v.z), "=f"(v.w) : "l"(p) : "memory");
    return v;
}
__device__ __forceinline__ void fence_gpu() {
    asm volatile("fence.acq_rel.gpu;" ::: "memory");
}
__device__ __forceinline__ float sigm_e(float x) { return 1.f / (1.f + __expf(-x)); }
__device__ __forceinline__ float tanh_e(float x) { return 1.f - 2.f / (1.f + __expf(2.f * x)); }
#define DOT4(a,b) ((a).x*(b).x + (a).y*(b).y + (a).z*(b).z + (a).w*(b).w)

// ----------------------------- fast SGEMM: 128x64 tile, 8x4 micro -----------
__global__ void __launch_bounds__(256) sgemm128(
    const float* __restrict__ A, int lda, long sA,
    const float* __restrict__ B, int ldb, long sB,
    float* __restrict__ C, int ldc, long sC,
    int M, int N, int K, const float* __restrict__ bias)
{
    __shared__ float As[16][132];
    __shared__ float Bs[16][64];

    const int tid = threadIdx.x;
    const int tx = tid & 15;
    const int ty = tid >> 4;
    const int m0 = blockIdx.y << 7, n0 = blockIdx.x << 6;
    A += (long)blockIdx.z * sA;
    B += (long)blockIdx.z * sB;
    C += (long)blockIdx.z * sC;

    const int ar = tid >> 2, ac4 = (tid & 3) << 2;
    const int br = tid >> 4, bc4 = (tid & 15) << 2;

    float acc[8][4];
#pragma unroll
    for (int i = 0; i < 8; i++)
#pragma unroll
        for (int j = 0; j < 4; j++) acc[i][j] = 0.f;

    for (int k0 = 0; k0 < K; k0 += 16) {
#pragma unroll
        for (int h = 0; h < 2; h++) {
            int m = ar + (h << 6);
            float4 v = *(const float4*)&A[(long)(m0 + m) * lda + k0 + ac4];
            As[ac4 + 0][m] = v.x;
            As[ac4 + 1][m] = v.y;
            As[ac4 + 2][m] = v.z;
            As[ac4 + 3][m] = v.w;
        }
        float4 bv = make_float4(0.f, 0.f, 0.f, 0.f);
        if (n0 + bc4 + 3 < N) {
            bv = *(const float4*)&B[(long)(k0 + br) * ldb + n0 + bc4];
        } else {
            float* p = (float*)&bv;
#pragma unroll
            for (int c = 0; c < 4; c++)
                if (n0 + bc4 + c < N) p[c] = B[(long)(k0 + br) * ldb + n0 + bc4 + c];
        }
        *(float4*)&Bs[br][bc4] = bv;
        __syncthreads();

#pragma unroll
        for (int k = 0; k < 16; k++) {
            float4 a0 = *(const float4*)&As[k][ty * 8];
            float4 a1 = *(const float4*)&As[k][ty * 8 + 4];
            float4 b4 = *(const float4*)&Bs[k][tx * 4];
            acc[0][0] += a0.x * b4.x; acc[0][1] += a0.x * b4.y; acc[0][2] += a0.x * b4.z; acc[0][3] += a0.x * b4.w;
            acc[1][0] += a0.y * b4.x; acc[1][1] += a0.y * b4.y; acc[1][2] += a0.y * b4.z; acc[1][3] += a0.y * b4.w;
            acc[2][0] += a0.z * b4.x; acc[2][1] += a0.z * b4.y; acc[2][2] += a0.z * b4.z; acc[2][3] += a0.z * b4.w;
            acc[3][0] += a0.w * b4.x; acc[3][1] += a0.w * b4.y; acc[3][2] += a0.w * b4.z; acc[3][3] += a0.w * b4.w;
            acc[4][0] += a1.x * b4.x; acc[4][1] += a1.x * b4.y; acc[4][2] += a1.x * b4.z; acc[4][3] += a1.x * b4.w;
            acc[5][0] += a1.y * b4.x; acc[5][1] += a1.y * b4.y; acc[5][2] += a1.y * b4.z; acc[5][3] += a1.y * b4.w;
            acc[6][0] += a1.z * b4.x; acc[6][1] += a1.z * b4.y; acc[6][2] += a1.z * b4.z; acc[6][3] += a1.z * b4.w;
            acc[7][0] += a1.w * b4.x; acc[7][1] += a1.w * b4.y; acc[7][2] += a1.w * b4.z; acc[7][3] += a1.w * b4.w;
        }
        __syncthreads();
    }

#pragma unroll
    for (int i = 0; i < 8; i++) {
        int m = m0 + ty * 8 + i;
#pragma unroll
        for (int j = 0; j < 4; j++) {
            int n = n0 + tx * 4 + j;
            if (n < N) {
                float v = acc[i][j];
                if (bias) v += bias[n];
                C[(long)m * ldc + n] = v;
            }
        }
    }
}

// ----------------------------- split-K partial reduce ------------------------
__global__ void __launch_bounds__(256) reduce_parts(
    const float* __restrict__ parts, long pstride, int nparts,
    const float* __restrict__ bias, int bmod, float* __restrict__ out, int n)
{
    int i = (blockIdx.x * 256 + threadIdx.x) << 2;
    if (i >= n) return;
    float4 a = *(const float4*)&parts[i];
    for (int p = 1; p < nparts; p++) {
        float4 b = *(const float4*)&parts[(long)p * pstride + i];
        a.x += b.x; a.y += b.y; a.z += b.z; a.w += b.w;
    }
    int bi = i % bmod;
    a.x += bias[bi]; a.y += bias[bi + 1]; a.z += bias[bi + 2]; a.w += bias[bi + 3];
    *(float4*)&out[i] = a;
}

// ----------------------------- persistent LSTM + fused h2 -------------------
// R11 champion; h2 fold moved to warps {1,2,3,5} so SMSP 0 holds ONLY the
// critical warp 0 during the gates/poll phase (hi-wid-first arbiter would
// otherwise prioritize warp 4's h2 work over warp 0 in SMSP 0).
__global__ void __launch_bounds__(256) lstm_kernel(
    const float* __restrict__ Wr, const float* __restrict__ W1,
    const float* __restrict__ b1, float* __restrict__ dout)
{
    extern __shared__ float s[];
    float* sWr = s;                         // [16 cols][512 k]   8192 f
    float* sh = s + 8192;                   // [8 b][512 k]       4096 f
    float* szred = s + 12288;               // [8 b][16 c]         128 f
    float* sW1 = s + 12416;                 // [4 c][512 k]       2048 f
    float* sB1 = s + 14464;                 // [4]
    const float4* sWrv = (const float4*)sWr;
    float4* shv = (float4*)sh;
    const float4* sW1v = (const float4*)sW1;
    __shared__ unsigned s_base;

    const int tid = threadIdx.x;
    const int hu0 = blockIdx.x << 2;
    const int lane = tid & 31, warp = tid >> 5;
    const int cb = warp & 3, bb = warp >> 2;  // col-block (=gate), batch-block
    const int gb = tid >> 2, gu = tid & 3;    // gate-thread mapping (tid<32)
    // h2-fold warp set {1,2,3,5}: SMSPs 1,2,3,1 — never SMSP 0
    const bool h2w = (warp >= 1 && warp <= 3) || (warp == 5);
    const int hw = (warp == 5) ? 3 : (warp - 1);   // 0..3 -> batches {2hw, 2hw+1}

    // stage Wr slice: sWr[c*512+k] = Wr[k][512*gate + hu0 + u]
    for (int idx = tid; idx < 8192; idx += 256) {
        int c = idx >> 9, k = idx & 511;
        int col = ((c >> 2) << 9) + hu0 + (c & 3);
        sWr[idx] = Wr[k * 2048 + col];
    }
    // stage W1 slice: sW1[c*512+k] = W1[k][hu0 + c]
    for (int idx = tid; idx < 2048; idx += 256) {
        int c = idx >> 9, k = idx & 511;
        sW1[idx] = W1[k * 512 + hu0 + c];
    }
    if (tid < 4) sB1[tid] = b1[hu0 + tid];

    if (tid == 0) s_base = ldg_relaxed_u32(&g_flags[blockIdx.x * 8]);
    if (tid < 32) stg_relaxed_f32(&g_hbuf[0][gb * 512 + hu0 + gu], 0.f);   // h0 = 0
    __syncthreads();
    const unsigned base = s_base;
    if (tid == 0) { fence_gpu(); stg_relaxed_u32(&g_flags[blockIdx.x * 8], base + 1u); }

    float creg = 0.f;

    for (int t = 0; t < TD; t++) {
        const int cur = t & 1, nxt = cur ^ 1;
        const unsigned tgt = base + (unsigned)t + 1u;

        // prefetch Xg for this step (overlaps the wait)
        float xg0 = 0.f, xg1 = 0.f, xg2 = 0.f, xg3 = 0.f;
        if (tid < 32) {
            const float* xr = &g_Xg[((gb << 8) + t) * 2048 + hu0 + gu];
            xg0 = xr[0]; xg1 = xr[512]; xg2 = xr[1024]; xg3 = xr[1536];
        }

        // all-poll-all barrier (R4 champion): warp 0 watches all 128 flags
        if (warp == 0) {
            bool ok;
            do {
                unsigned f0 = ldg_relaxed_u32(&g_flags[(lane) * 8]);
                unsigned f1 = ldg_relaxed_u32(&g_flags[(lane + 32) * 8]);
                unsigned f2 = ldg_relaxed_u32(&g_flags[(lane + 64) * 8]);
                unsigned f3 = ldg_relaxed_u32(&g_flags[(lane + 96) * 8]);
                ok = ((int)(f0 - tgt) >= 0) & ((int)(f1 - tgt) >= 0) &
                     ((int)(f2 - tgt) >= 0) & ((int)(f3 - tgt) >= 0);
            } while (!__all_sync(0xffffffffu, ok));
            fence_gpu();
        }
        __syncthreads();

        // stage h(t) = x[t-1] into SMEM
        const float4* src = (const float4*)g_hbuf[cur];
#pragma unroll
        for (int i = 0; i < 4; i++) shv[tid + (i << 8)] = ldg_relaxed_f4(&src[tid + (i << 8)]);
        __syncthreads();

        // GEMV: warp (cb,bb) computes z[bb*4..+3][cb*4..+3], k lane-vectorized
        float acc[4][4];
#pragma unroll
        for (int i = 0; i < 4; i++)
#pragma unroll
            for (int j = 0; j < 4; j++) acc[i][j] = 0.f;

#pragma unroll
        for (int kk = 0; kk < 4; kk++) {
            const int kv = (kk << 5) + lane;
            float4 h0 = shv[((bb << 2) + 0) * 128 + kv];
            float4 h1 = shv[((bb << 2) + 1) * 128 + kv];
            float4 h2 = shv[((bb << 2) + 2) * 128 + kv];
            float4 h3 = shv[((bb << 2) + 3) * 128 + kv];
            float4 w0 = sWrv[((cb << 2) + 0) * 128 + kv];
            float4 w1 = sWrv[((cb << 2) + 1) * 128 + kv];
            float4 w2 = sWrv[((cb << 2) + 2) * 128 + kv];
            float4 w3 = sWrv[((cb << 2) + 3) * 128 + kv];
            acc[0][0] += DOT4(h0, w0); acc[0][1] += DOT4(h0, w1); acc[0][2] += DOT4(h0, w2); acc[0][3] += DOT4(h0, w3);
            acc[1][0] += DOT4(h1, w0); acc[1][1] += DOT4(h1, w1); acc[1][2] += DOT4(h1, w2); acc[1][3] += DOT4(h1, w3);
            acc[2][0] += DOT4(h2, w0); acc[2][1] += DOT4(h2, w1); acc[2][2] += DOT4(h2, w2); acc[2][3] += DOT4(h2, w3);
            acc[3][0] += DOT4(h3, w0); acc[3][1] += DOT4(h3, w1); acc[3][2] += DOT4(h3, w2); acc[3][3] += DOT4(h3, w3);
        }

        // butterfly reduce over 32 k-lanes
#pragma unroll
        for (int off = 16; off; off >>= 1)
#pragma unroll
            for (int i = 0; i < 4; i++)
#pragma unroll
                for (int j = 0; j < 4; j++)
                    acc[i][j] += __shfl_xor_sync(0xffffffffu, acc[i][j], off);

        if (lane < 16) {
            int i = lane >> 2, j = lane & 3;
            szred[((bb << 2) + i) * 16 + ((cb << 2) + j)] = acc[i][j];
        }
        __syncthreads();

        // warp 0: gates (critical path, alone in SMSP 0). warps {1,2,3,5}: h2.
        if (tid < 32) {
            float zi = szred[gb * 16 + 0 + gu] + xg0;
            float zf = szred[gb * 16 + 4 + gu] + xg1;
            float zg = szred[gb * 16 + 8 + gu] + xg2;
            float zo = szred[gb * 16 + 12 + gu] + xg3;
            float ig = sigm_e(zi);
            float fg = sigm_e(zf);
            float gg = tanh_e(zg);
            float og = sigm_e(zo);
            creg = fg * creg + ig * gg;
            float h = og * tanh_e(creg);
            stg_relaxed_f32(&g_hbuf[nxt][gb * 512 + hu0 + gu], h);
            g_XC[((gb << 8) + t) * 1024 + hu0 + gu] = h;   // x sequence
            if (t == TD - 1) {
                dout[ROWS * MEL + gb * 512 + hu0 + gu] = h;                 // state_h
                dout[ROWS * MEL + BATCH * D + gb * 512 + hu0 + gu] = creg;  // state_c
            }
            fence_gpu();
            __syncwarp();
            if (tid == 0) stg_relaxed_u32(&g_flags[blockIdx.x * 8], base + (unsigned)t + 2u);
        } else if (h2w && t > 0) {
            const int trow = t - 1;
            float a0c[4] = {0.f, 0.f, 0.f, 0.f};
            float a1c[4] = {0.f, 0.f, 0.f, 0.f};
#pragma unroll
            for (int j = 0; j < 4; j++) {
                const int k4 = (j << 5) + lane;
                float4 hA = shv[((hw << 1) + 0) * 128 + k4];
                float4 hB = shv[((hw << 1) + 1) * 128 + k4];
#pragma unroll
                for (int c = 0; c < 4; c++) {
                    float4 wv = sW1v[c * 128 + k4];
                    a0c[c] += DOT4(hA, wv);
                    a1c[c] += DOT4(hB, wv);
                }
            }
#pragma unroll
            for (int off = 16; off; off >>= 1)
#pragma unroll
                for (int c = 0; c < 4; c++) {
                    a0c[c] += __shfl_xor_sync(0xffffffffu, a0c[c], off);
                    a1c[c] += __shfl_xor_sync(0xffffffffu, a1c[c], off);
                }
#pragma unroll
            for (int c = 0; c < 4; c++) {
                if (lane == c)
                    g_h2[(((hw << 1) << 8) | trow) * 512 + hu0 + c] = a0c[c] + sB1[c];
                if (lane == 4 + c)
                    g_h2[((((hw << 1) + 1) << 8) | trow) * 512 + hu0 + c] = a1c[c] + sB1[c];
            }
        }
    }

    // tail: h2 row TD-1 needs x[TD-1] = h(256), which lives in g_hbuf[0]
    {
        const unsigned tgt = base + (unsigned)TD + 1u;
        if (warp == 0) {
            bool ok;
            do {
                unsigned f0 = ldg_relaxed_u32(&g_flags[(lane) * 8]);
                unsigned f1 = ldg_relaxed_u32(&g_flags[(lane + 32) * 8]);
                unsigned f2 = ldg_relaxed_u32(&g_flags[(lane + 64) * 8]);
                unsigned f3 = ldg_relaxed_u32(&g_flags[(lane + 96) * 8]);
                ok = ((int)(f0 - tgt) >= 0) & ((int)(f1 - tgt) >= 0) &
                     ((int)(f2 - tgt) >= 0) & ((int)(f3 - tgt) >= 0);
            } while (!__all_sync(0xffffffffu, ok));
            fence_gpu();
        }
        __syncthreads();
        const float4* src = (const float4*)g_hbuf[0];
#pragma unroll
        for (int i = 0; i < 4; i++) shv[tid + (i << 8)] = ldg_relaxed_f4(&src[tid + (i << 8)]);
        __syncthreads();
        if (h2w) {
            float a0c[4] = {0.f, 0.f, 0.f, 0.f};
            float a1c[4] = {0.f, 0.f, 0.f, 0.f};
#pragma unroll
            for (int j = 0; j < 4; j++) {
                const int k4 = (j << 5) + lane;
                float4 hA = shv[((hw << 1) + 0) * 128 + k4];
                float4 hB = shv[((hw << 1) + 1) * 128 + k4];
#pragma unroll
                for (int c = 0; c < 4; c++) {
                    float4 wv = sW1v[c * 128 + k4];
                    a0c[c] += DOT4(hA, wv);
                    a1c[c] += DOT4(hB, wv);
                }
            }
#pragma unroll
            for (int off = 16; off; off >>= 1)
#pragma unroll
                for (int c = 0; c < 4; c++) {
                    a0c[c] += __shfl_xor_sync(0xffffffffu, a0c[c], off);
                    a1c[c] += __shfl_xor_sync(0xffffffffu, a1c[c], off);
                }
#pragma unroll
            for (int c = 0; c < 4; c++) {
                if (lane == c)
                    g_h2[(((hw << 1) << 8) | (TD - 1)) * 512 + hu0 + c] = a0c[c] + sB1[c];
                if (lane == 4 + c)
                    g_h2[((((hw << 1) + 1) << 8) | (TD - 1)) * 512 + hu0 + c] = a1c[c] + sB1[c];
            }
        }
    }
}

// ----------------------------- attention scores -----------------------------
__global__ void __launch_bounds__(256) scores_kernel(const float* __restrict__ W3)
{
    __shared__ float sh1[64 * 65];
    __shared__ float sh2[16 * 64];
    __shared__ float sW3[512];

    const int tid = threadIdx.x;
    const int bz = blockIdx.z, t0 = blockIdx.y << 4, e0 = blockIdx.x << 6;
    const int e = tid & 63, tg = tid >> 6;

    sW3[tid] = W3[tid];
    sW3[tid + 256] = W3[tid + 256];

    float acc[4] = {0.f, 0.f, 0.f, 0.f};

    for (int dc = 0; dc < 512; dc += 64) {
        __syncthreads();
#pragma unroll
        for (int i = 0; i < 4; i++) {
            int q = tid + (i << 8);
            int er = q >> 4, d4 = (q & 15) << 2;
            float4 v = *(const float4*)&g_h1[(long)(bz * 256 + e0 + er) * 512 + dc + d4];
            sh1[(d4 + 0) * 65 + er] = v.x;
            sh1[(d4 + 1) * 65 + er] = v.y;
            sh1[(d4 + 2) * 65 + er] = v.z;
            sh1[(d4 + 3) * 65 + er] = v.w;
        }
        {
            int tt = tid >> 4, d4 = (tid & 15) << 2;
            float4 v = *(const float4*)&g_h2[(long)(bz * 256 + t0 + tt) * 512 + dc + d4];
            *(float4*)&sh2[tt * 64 + d4] = v;
        }
        __syncthreads();

#pragma unroll 8
        for (int d = 0; d < 64; d++) {
            float h1v = sh1[d * 65 + e];
            float w = sW3[dc + d];
#pragma unroll
            for (int i = 0; i < 4; i++) {
                float v = h1v + sh2[(tg * 4 + i) * 64 + d];
                acc[i] += fast_tanh(v) * w;
            }
        }
    }

#pragma unroll
    for (int i = 0; i < 4; i++)
        g_scores[(long)(bz * 256 + t0 + tg * 4 + i) * 256 + e0 + e] = acc[i];
}

// ----------------------------- row softmax (in place) -----------------------
__global__ void __launch_bounds__(256) softmax_kernel()
{
    float* p = g_scores + (long)blockIdx.x * 256;
    const int tid = threadIdx.x;
    const int lane = tid & 31, w = tid >> 5;
    __shared__ float redm[8];
    __shared__ float reds[8];

    float v = p[tid];
    float m = v;
#pragma unroll
    for (int o = 16; o; o >>= 1) m = fmaxf(m, __shfl_xor_sync(0xffffffffu, m, o));
    if (lane == 0) redm[w] = m;
    __syncthreads();
    if (tid < 32) {
        float x = (tid < 8) ? redm[tid] : -1e30f;
#pragma unroll
        for (int o = 4; o; o >>= 1) x = fmaxf(x, __shfl_xor_sync(0xffffffffu, x, o));
        if (tid == 0) redm[0] = x;
    }
    __syncthreads();
    float ev = __expf(v - redm[0]);
    float ssum = ev;
#pragma unroll
    for (int o = 16; o; o >>= 1) ssum += __shfl_xor_sync(0xffffffffu, ssum, o);
    if (lane == 0) reds[w] = ssum;
    __syncthreads();
    if (tid < 32) {
        float x = (tid < 8) ? reds[tid] : 0.f;
#pragma unroll
        for (int o = 4; o; o >>= 1) x += __shfl_xor_sync(0xffffffffu, x, o);
        if (tid == 0) reds[0] = x;
    }
    __syncthreads();
    p[tid] = ev / reds[0];
}

// ----------------------------- launch ---------------------------------------
extern "C" void kernel_launch(void* const* d_in, const int* in_sizes, int n_in,
                              void* d_out, int out_size)
{
    const float* inputs   = (const float*)d_in[0];
    const float* attended = (const float*)d_in[1];
    const float* Wk       = (const float*)d_in[2];
    const float* Wr       = (const float*)d_in[3];
    const float* lstm_b   = (const float*)d_in[4];
    const float* W1       = (const float*)d_in[5];
    const float* b1       = (const float*)d_in[6];
    const float* W3       = (const float*)d_in[7];
    /* b3 (d_in[8]) cancels in softmax */
    const float* Wout     = (const float*)d_in[9];
    const float* bout     = (const float*)d_in[10];
    float* dout = (float*)d_out;

    static float* pXg = nullptr;
    static float* pH1 = nullptr;
    static float* pH2 = nullptr;
    static float* pXC = nullptr;
    static float* pSc = nullptr;
    static float* pPt = nullptr;
    static cudaStream_t s1 = nullptr;
    static cudaEvent_t evA = nullptr, evB = nullptr;
    static bool attr_done = false;
    if (!pXg) {
        cudaGetSymbolAddress((void**)&pXg, g_Xg);
        cudaGetSymbolAddress((void**)&pH1, g_h1);
        cudaGetSymbolAddress((void**)&pH2, g_h2);
        cudaGetSymbolAddress((void**)&pXC, g_XC);
        cudaGetSymbolAddress((void**)&pSc, g_scores);
        cudaGetSymbolAddress((void**)&pPt, g_part);
    }
    const int LSTM_SMEM = 14468 * 4;   // 57,872 B
    if (!attr_done) {
        cudaFuncSetAttribute(lstm_kernel, cudaFuncAttributeMaxDynamicSharedMemorySize,
                             LSTM_SMEM);
        cudaStreamCreateWithFlags(&s1, cudaStreamNonBlocking);
        cudaEventCreateWithFlags(&evA, cudaEventDisableTiming);
        cudaEventCreateWithFlags(&evB, cudaEventDisableTiming);
        attr_done = true;
    }
    const long PS = (long)ROWS * D;

    // fork side stream: h1 = attended @ W1 + b1 (independent of LSTM chain)
    cudaEventRecord(evA, 0);
    cudaStreamWaitEvent(s1, evA, 0);
    sgemm128<<<dim3(8, 16, 2), 256, 0, s1>>>(attended, D, 256, W1, D, 256L * D,
                                             pPt + 2 * PS, D, PS, ROWS, D, 256, nullptr);
    reduce_parts<<<PS / 1024, 256, 0, s1>>>(pPt + 2 * PS, PS, 2, b1, D, pH1, (int)PS);
    cudaEventRecord(evB, s1);

    // main stream: Xg -> LSTM(+h2 fold) -> (join h1) scores -> softmax -> weighted -> out
    sgemm128<<<dim3(32, 16, 1), 256>>>(inputs, DIN, 0, Wk, 4 * D, 0,
                                       pXg, 4 * D, 0, ROWS, 4 * D, DIN, lstm_b);
    lstm_kernel<<<NBLK_LSTM, 256, LSTM_SMEM>>>(Wr, W1, b1, dout);

    cudaStreamWaitEvent(0, evB, 0);   // join h1 before scores
    scores_kernel<<<dim3(4, 16, 8), 256>>>(W3);
    softmax_kernel<<<ROWS, 256>>>();
    sgemm128<<<dim3(8, 2, 8), 256>>>(pSc, TE, (long)TD * TE,
                                     attended, D, (long)TE * D,
                                     pXC + D, 2 * D, (long)TD * 2 * D,
                                     TD, D, TE, nullptr);
    {
        const long OS = (long)ROWS * MEL;
        sgemm128<<<dim3(2, 16, 4), 256>>>(pXC, 2 * D, 256, Wout, MEL, 256L * MEL,
                                          pPt, MEL, OS, ROWS, MEL, 256, nullptr);
        reduce_parts<<<(unsigned)(OS / 1024), 256>>>(pPt, OS, 4, bout, MEL, dout, (int)OS);
    }
}

// round 16
// speedup vs baseline: 1.4831x; 1.0433x over previous
#include <cuda_runtime.h>
#include <math.h>

#define BATCH 8
#define TD 256
#define TE 256
#define DIN 80
#define D 512
#define MEL 80
#define ROWS (BATCH*TD)          // 2048
#define NBLK_LSTM 128

// ----------------------------- scratch (device globals) ---------------------
__device__ __align__(16) float g_Xg[ROWS * 4 * D];        // inputs@Wk + b : [2048][2048]
__device__ __align__(16) float g_h1[ROWS * D];            // attended@W1+b1: [2048][512]
__device__ __align__(16) float g_h2[ROWS * D];            // x@W1+b1      : [2048][512]
__device__ __align__(16) float g_XC[ROWS * 2 * D];        // [x | weighted]: [2048][1024]
__device__ __align__(16) float g_scores[BATCH * TD * TE]; // scores/attn   : [2048][256]
__device__ __align__(16) float g_part[4 * ROWS * D];      // split-K partials
__device__ __align__(16) float g_hbuf[2][BATCH * D];      // double-buffered h
__device__ __align__(16) unsigned g_pfl[NBLK_LSTM];       // packed per-CTA flags (contiguous)

// ----------------------------- helpers --------------------------------------
__device__ __forceinline__ float fast_tanh(float x) {
    float y;
    asm("tanh.approx.f32 %0, %1;" : "=f"(y) : "f"(x));
    return y;
}
__device__ __forceinline__ unsigned ldg_relaxed_u32(const unsigned* p) {
    unsigned v;
    asm volatile("ld.relaxed.gpu.global.u32 %0, [%1];" : "=r"(v) : "l"(p) : "memory");
    return v;
}
__device__ __forceinline__ uint4 ldg_relaxed_u4(const uint4* p) {
    uint4 v;
    asm volatile("ld.relaxed.gpu.global.v4.u32 {%0,%1,%2,%3}, [%4];"
                 : "=r"(v.x), "=r"(v.y), "=r"(v.z), "=r"(v.w) : "l"(p) : "memory");
    return v;
}
__device__ __forceinline__ void stg_relaxed_u32(unsigned* p, unsigned v) {
    asm volatile("st.relaxed.gpu.global.u32 [%0], %1;" :: "l"(p), "r"(v) : "memory");
}
__device__ __forceinline__ void stg_relaxed_f32(float* p, float v) {
    asm volatile("st.relaxed.gpu.global.f32 [%0], %1;" :: "l"(p), "f"(v) : "memory");
}
__device__ __forceinline__ float4 ldg_relaxed_f4(const float4* p) {
    float4 v;
    asm volatile("ld.relaxed.gpu.global.v4.f32 {%0,%1,%2,%3}, [%4];"
                 : "=f"(v.x), "=f"(v.y), "=f"(v.z), "=f"(v.w) : "l"(p) : "memory");
    return v;
}
__device__ __forceinline__ void fence_gpu() {
    asm volatile("fence.acq_rel.gpu;" ::: "memory");
}
__device__ __forceinline__ float sigm_e(float x) { return 1.f / (1.f + __expf(-x)); }
__device__ __forceinline__ float tanh_e(float x) { return 1.f - 2.f / (1.f + __expf(2.f * x)); }
#define DOT4(a,b) ((a).x*(b).x + (a).y*(b).y + (a).z*(b).z + (a).w*(b).w)

// ----------------------------- fast SGEMM: 128x64 tile, 8x4 micro -----------
__global__ void __launch_bounds__(256) sgemm128(
    const float* __restrict__ A, int lda, long sA,
    const float* __restrict__ B, int ldb, long sB,
    float* __restrict__ C, int ldc, long sC,
    int M, int N, int K, const float* __restrict__ bias)
{
    __shared__ float As[16][132];
    __shared__ float Bs[16][64];

    const int tid = threadIdx.x;
    const int tx = tid & 15;
    const int ty = tid >> 4;
    const int m0 = blockIdx.y << 7, n0 = blockIdx.x << 6;
    A += (long)blockIdx.z * sA;
    B += (long)blockIdx.z * sB;
    C += (long)blockIdx.z * sC;

    const int ar = tid >> 2, ac4 = (tid & 3) << 2;
    const int br = tid >> 4, bc4 = (tid & 15) << 2;

    float acc[8][4];
#pragma unroll
    for (int i = 0; i < 8; i++)
#pragma unroll
        for (int j = 0; j < 4; j++) acc[i][j] = 0.f;

    for (int k0 = 0; k0 < K; k0 += 16) {
#pragma unroll
        for (int h = 0; h < 2; h++) {
            int m = ar + (h << 6);
            float4 v = *(const float4*)&A[(long)(m0 + m) * lda + k0 + ac4];
            As[ac4 + 0][m] = v.x;
            As[ac4 + 1][m] = v.y;
            As[ac4 + 2][m] = v.z;
            As[ac4 + 3][m] = v.w;
        }
        float4 bv = make_float4(0.f, 0.f, 0.f, 0.f);
        if (n0 + bc4 + 3 < N) {
            bv = *(const float4*)&B[(long)(k0 + br) * ldb + n0 + bc4];
        } else {
            float* p = (float*)&bv;
#pragma unroll
            for (int c = 0; c < 4; c++)
                if (n0 + bc4 + c < N) p[c] = B[(long)(k0 + br) * ldb + n0 + bc4 + c];
        }
        *(float4*)&Bs[br][bc4] = bv;
        __syncthreads();

#pragma unroll
        for (int k = 0; k < 16; k++) {
            float4 a0 = *(const float4*)&As[k][ty * 8];
            float4 a1 = *(const float4*)&As[k][ty * 8 + 4];
            float4 b4 = *(const float4*)&Bs[k][tx * 4];
            acc[0][0] += a0.x * b4.x; acc[0][1] += a0.x * b4.y; acc[0][2] += a0.x * b4.z; acc[0][3] += a0.x * b4.w;
            acc[1][0] += a0.y * b4.x; acc[1][1] += a0.y * b4.y; acc[1][2] += a0.y * b4.z; acc[1][3] += a0.y * b4.w;
            acc[2][0] += a0.z * b4.x; acc[2][1] += a0.z * b4.y; acc[2][2] += a0.z * b4.z; acc[2][3] += a0.z * b4.w;
            acc[3][0] += a0.w * b4.x; acc[3][1] += a0.w * b4.y; acc[3][2] += a0.w * b4.z; acc[3][3] += a0.w * b4.w;
            acc[4][0] += a1.x * b4.x; acc[4][1] += a1.x * b4.y; acc[4][2] += a1.x * b4.z; acc[4][3] += a1.x * b4.w;
            acc[5][0] += a1.y * b4.x; acc[5][1] += a1.y * b4.y; acc[5][2] += a1.y * b4.z; acc[5][3] += a1.y * b4.w;
            acc[6][0] += a1.z * b4.x; acc[6][1] += a1.z * b4.y; acc[6][2] += a1.z * b4.z; acc[6][3] += a1.z * b4.w;
            acc[7][0] += a1.w * b4.x; acc[7][1] += a1.w * b4.y; acc[7][2] += a1.w * b4.z; acc[7][3] += a1.w * b4.w;
        }
        __syncthreads();
    }

#pragma unroll
    for (int i = 0; i < 8; i++) {
        int m = m0 + ty * 8 + i;
#pragma unroll
        for (int j = 0; j < 4; j++) {
            int n = n0 + tx * 4 + j;
            if (n < N) {
                float v = acc[i][j];
                if (bias) v += bias[n];
                C[(long)m * ldc + n] = v;
            }
        }
    }
}

// ----------------------------- split-K partial reduce ------------------------
__global__ void __launch_bounds__(256) reduce_parts(
    const float* __restrict__ parts, long pstride, int nparts,
    const float* __restrict__ bias, int bmod, float* __restrict__ out, int n)
{
    int i = (blockIdx.x * 256 + threadIdx.x) << 2;
    if (i >= n) return;
    float4 a = *(const float4*)&parts[i];
    for (int p = 1; p < nparts; p++) {
        float4 b = *(const float4*)&parts[(long)p * pstride + i];
        a.x += b.x; a.y += b.y; a.z += b.z; a.w += b.w;
    }
    int bi = i % bmod;
    a.x += bias[bi]; a.y += bias[bi + 1]; a.z += bias[bi + 2]; a.w += bias[bi + 3];
    *(float4*)&out[i] = a;
}

// ----------------------------- persistent LSTM + fused h2 -------------------
// R15 champion + vectorized poll: packed contiguous flags, all 128 checked
// with ONE ld.relaxed.v4.u32 per lane per poll iteration.
__global__ void __launch_bounds__(256) lstm_kernel(
    const float* __restrict__ Wr, const float* __restrict__ W1,
    const float* __restrict__ b1, float* __restrict__ dout)
{
    extern __shared__ float s[];
    float* sWr = s;                         // [16 cols][512 k]   8192 f
    float* sh = s + 8192;                   // [8 b][512 k]       4096 f
    float* szred = s + 12288;               // [8 b][16 c]         128 f
    float* sW1 = s + 12416;                 // [4 c][512 k]       2048 f
    float* sB1 = s + 14464;                 // [4]
    const float4* sWrv = (const float4*)sWr;
    float4* shv = (float4*)sh;
    const float4* sW1v = (const float4*)sW1;
    __shared__ unsigned s_base;

    const int tid = threadIdx.x;
    const int hu0 = blockIdx.x << 2;
    const int lane = tid & 31, warp = tid >> 5;
    const int cb = warp & 3, bb = warp >> 2;  // col-block (=gate), batch-block
    const int gb = tid >> 2, gu = tid & 3;    // gate-thread mapping (tid<32)
    // h2-fold warp set {1,2,3,5}: SMSPs 1,2,3,1 — never SMSP 0
    const bool h2w = (warp >= 1 && warp <= 3) || (warp == 5);
    const int hw = (warp == 5) ? 3 : (warp - 1);   // 0..3 -> batches {2hw, 2hw+1}

    // stage Wr slice: sWr[c*512+k] = Wr[k][512*gate + hu0 + u]
    for (int idx = tid; idx < 8192; idx += 256) {
        int c = idx >> 9, k = idx & 511;
        int col = ((c >> 2) << 9) + hu0 + (c & 3);
        sWr[idx] = Wr[k * 2048 + col];
    }
    // stage W1 slice: sW1[c*512+k] = W1[k][hu0 + c]
    for (int idx = tid; idx < 2048; idx += 256) {
        int c = idx >> 9, k = idx & 511;
        sW1[idx] = W1[k * 512 + hu0 + c];
    }
    if (tid < 4) sB1[tid] = b1[hu0 + tid];

    if (tid == 0) s_base = ldg_relaxed_u32(&g_pfl[blockIdx.x]);
    if (tid < 32) stg_relaxed_f32(&g_hbuf[0][gb * 512 + hu0 + gu], 0.f);   // h0 = 0
    __syncthreads();
    const unsigned base = s_base;
    if (tid == 0) { fence_gpu(); stg_relaxed_u32(&g_pfl[blockIdx.x], base + 1u); }

    float creg = 0.f;

    for (int t = 0; t < TD; t++) {
        const int cur = t & 1, nxt = cur ^ 1;
        const unsigned tgt = base + (unsigned)t + 1u;

        // prefetch Xg for this step (overlaps the wait)
        float xg0 = 0.f, xg1 = 0.f, xg2 = 0.f, xg3 = 0.f;
        if (tid < 32) {
            const float* xr = &g_Xg[((gb << 8) + t) * 2048 + hu0 + gu];
            xg0 = xr[0]; xg1 = xr[512]; xg2 = xr[1024]; xg3 = xr[1536];
        }

        // vectorized all-poll-all barrier: lane l checks CTAs 4l..4l+3
        if (warp == 0) {
            const uint4* fp = (const uint4*)g_pfl;
            bool ok;
            do {
                uint4 f = ldg_relaxed_u4(&fp[lane]);
                ok = ((int)(f.x - tgt) >= 0) & ((int)(f.y - tgt) >= 0) &
                     ((int)(f.z - tgt) >= 0) & ((int)(f.w - tgt) >= 0);
            } while (!__all_sync(0xffffffffu, ok));
            fence_gpu();
        }
        __syncthreads();

        // stage h(t) = x[t-1] into SMEM
        const float4* src = (const float4*)g_hbuf[cur];
#pragma unroll
        for (int i = 0; i < 4; i++) shv[tid + (i << 8)] = ldg_relaxed_f4(&src[tid + (i << 8)]);
        __syncthreads();

        // GEMV: warp (cb,bb) computes z[bb*4..+3][cb*4..+3], k lane-vectorized
        float acc[4][4];
#pragma unroll
        for (int i = 0; i < 4; i++)
#pragma unroll
            for (int j = 0; j < 4; j++) acc[i][j] = 0.f;

#pragma unroll
        for (int kk = 0; kk < 4; kk++) {
            const int kv = (kk << 5) + lane;
            float4 h0 = shv[((bb << 2) + 0) * 128 + kv];
            float4 h1 = shv[((bb << 2) + 1) * 128 + kv];
            float4 h2 = shv[((bb << 2) + 2) * 128 + kv];
            float4 h3 = shv[((bb << 2) + 3) * 128 + kv];
            float4 w0 = sWrv[((cb << 2) + 0) * 128 + kv];
            float4 w1 = sWrv[((cb << 2) + 1) * 128 + kv];
            float4 w2 = sWrv[((cb << 2) + 2) * 128 + kv];
            float4 w3 = sWrv[((cb << 2) + 3) * 128 + kv];
            acc[0][0] += DOT4(h0, w0); acc[0][1] += DOT4(h0, w1); acc[0][2] += DOT4(h0, w2); acc[0][3] += DOT4(h0, w3);
            acc[1][0] += DOT4(h1, w0); acc[1][1] += DOT4(h1, w1); acc[1][2] += DOT4(h1, w2); acc[1][3] += DOT4(h1, w3);
            acc[2][0] += DOT4(h2, w0); acc[2][1] += DOT4(h2, w1); acc[2][2] += DOT4(h2, w2); acc[2][3] += DOT4(h2, w3);
            acc[3][0] += DOT4(h3, w0); acc[3][1] += DOT4(h3, w1); acc[3][2] += DOT4(h3, w2); acc[3][3] += DOT4(h3, w3);
        }

        // butterfly reduce over 32 k-lanes
#pragma unroll
        for (int off = 16; off; off >>= 1)
#pragma unroll
            for (int i = 0; i < 4; i++)
#pragma unroll
                for (int j = 0; j < 4; j++)
                    acc[i][j] += __shfl_xor_sync(0xffffffffu, acc[i][j], off);

        if (lane < 16) {
            int i = lane >> 2, j = lane & 3;
            szred[((bb << 2) + i) * 16 + ((cb << 2) + j)] = acc[i][j];
        }
        __syncthreads();

        // warp 0: gates (critical path, alone in SMSP 0). warps {1,2,3,5}: h2.
        if (tid < 32) {
            float zi = szred[gb * 16 + 0 + gu] + xg0;
            float zf = szred[gb * 16 + 4 + gu] + xg1;
            float zg = szred[gb * 16 + 8 + gu] + xg2;
            float zo = szred[gb * 16 + 12 + gu] + xg3;
            float ig = sigm_e(zi);
            float fg = sigm_e(zf);
            float gg = tanh_e(zg);
            float og = sigm_e(zo);
            creg = fg * creg + ig * gg;
            float h = og * tanh_e(creg);
            stg_relaxed_f32(&g_hbuf[nxt][gb * 512 + hu0 + gu], h);
            g_XC[((gb << 8) + t) * 1024 + hu0 + gu] = h;   // x sequence
            if (t == TD - 1) {
                dout[ROWS * MEL + gb * 512 + hu0 + gu] = h;                 // state_h
                dout[ROWS * MEL + BATCH * D + gb * 512 + hu0 + gu] = creg;  // state_c
            }
            fence_gpu();
            __syncwarp();
            if (tid == 0) stg_relaxed_u32(&g_pfl[blockIdx.x], base + (unsigned)t + 2u);
        } else if (h2w && t > 0) {
            const int trow = t - 1;
            float a0c[4] = {0.f, 0.f, 0.f, 0.f};
            float a1c[4] = {0.f, 0.f, 0.f, 0.f};
#pragma unroll
            for (int j = 0; j < 4; j++) {
                const int k4 = (j << 5) + lane;
                float4 hA = shv[((hw << 1) + 0) * 128 + k4];
                float4 hB = shv[((hw << 1) + 1) * 128 + k4];
#pragma unroll
                for (int c = 0; c < 4; c++) {
                    float4 wv = sW1v[c * 128 + k4];
                    a0c[c] += DOT4(hA, wv);
                    a1c[c] += DOT4(hB, wv);
                }
            }
#pragma unroll
            for (int off = 16; off; off >>= 1)
#pragma unroll
                for (int c = 0; c < 4; c++) {
                    a0c[c] += __shfl_xor_sync(0xffffffffu, a0c[c], off);
                    a1c[c] += __shfl_xor_sync(0xffffffffu, a1c[c], off);
                }
#pragma unroll
            for (int c = 0; c < 4; c++) {
                if (lane == c)
                    g_h2[(((hw << 1) << 8) | trow) * 512 + hu0 + c] = a0c[c] + sB1[c];
                if (lane == 4 + c)
                    g_h2[((((hw << 1) + 1) << 8) | trow) * 512 + hu0 + c] = a1c[c] + sB1[c];
            }
        }
    }

    // tail: h2 row TD-1 needs x[TD-1] = h(256), which lives in g_hbuf[0]
    {
        const unsigned tgt = base + (unsigned)TD + 1u;
        if (warp == 0) {
            const uint4* fp = (const uint4*)g_pfl;
            bool ok;
            do {
                uint4 f = ldg_relaxed_u4(&fp[lane]);
                ok = ((int)(f.x - tgt) >= 0) & ((int)(f.y - tgt) >= 0) &
                     ((int)(f.z - tgt) >= 0) & ((int)(f.w - tgt) >= 0);
            } while (!__all_sync(0xffffffffu, ok));
            fence_gpu();
        }
        __syncthreads();
        const float4* src = (const float4*)g_hbuf[0];
#pragma unroll
        for (int i = 0; i < 4; i++) shv[tid + (i << 8)] = ldg_relaxed_f4(&src[tid + (i << 8)]);
        __syncthreads();
        if (h2w) {
            float a0c[4] = {0.f, 0.f, 0.f, 0.f};
            float a1c[4] = {0.f, 0.f, 0.f, 0.f};
#pragma unroll
            for (int j = 0; j < 4; j++) {
                const int k4 = (j << 5) + lane;
                float4 hA = shv[((hw << 1) + 0) * 128 + k4];
                float4 hB = shv[((hw << 1) + 1) * 128 + k4];
#pragma unroll
                for (int c = 0; c < 4; c++) {
                    float4 wv = sW1v[c * 128 + k4];
                    a0c[c] += DOT4(hA, wv);
                    a1c[c] += DOT4(hB, wv);
                }
            }
#pragma unroll
            for (int off = 16; off; off >>= 1)
#pragma unroll
                for (int c = 0; c < 4; c++) {
                    a0c[c] += __shfl_xor_sync(0xffffffffu, a0c[c], off);
                    a1c[c] += __shfl_xor_sync(0xffffffffu, a1c[c], off);
                }
#pragma unroll
            for (int c = 0; c < 4; c++) {
                if (lane == c)
                    g_h2[(((hw << 1) << 8) | (TD - 1)) * 512 + hu0 + c] = a0c[c] + sB1[c];
                if (lane == 4 + c)
                    g_h2[((((hw << 1) + 1) << 8) | (TD - 1)) * 512 + hu0 + c] = a1c[c] + sB1[c];
            }
        }
    }
}

// ----------------------------- attention scores -----------------------------
__global__ void __launch_bounds__(256) scores_kernel(const float* __restrict__ W3)
{
    __shared__ float sh1[64 * 65];
    __shared__ float sh2[16 * 64];
    __shared__ float sW3[512];

    const int tid = threadIdx.x;
    const int bz = blockIdx.z, t0 = blockIdx.y << 4, e0 = blockIdx.x << 6;
    const int e = tid & 63, tg = tid >> 6;

    sW3[tid] = W3[tid];
    sW3[tid + 256] = W3[tid + 256];

    float acc[4] = {0.f, 0.f, 0.f, 0.f};

    for (int dc = 0; dc < 512; dc += 64) {
        __syncthreads();
#pragma unroll
        for (int i = 0; i < 4; i++) {
            int q = tid + (i << 8);
            int er = q >> 4, d4 = (q & 15) << 2;
            float4 v = *(const float4*)&g_h1[(long)(bz * 256 + e0 + er) * 512 + dc + d4];
            sh1[(d4 + 0) * 65 + er] = v.x;
            sh1[(d4 + 1) * 65 + er] = v.y;
            sh1[(d4 + 2) * 65 + er] = v.z;
            sh1[(d4 + 3) * 65 + er] = v.w;
        }
        {
            int tt = tid >> 4, d4 = (tid & 15) << 2;
            float4 v = *(const float4*)&g_h2[(long)(bz * 256 + t0 + tt) * 512 + dc + d4];
            *(float4*)&sh2[tt * 64 + d4] = v;
        }
        __syncthreads();

#pragma unroll 8
        for (int d = 0; d < 64; d++) {
            float h1v = sh1[d * 65 + e];
            float w = sW3[dc + d];
#pragma unroll
            for (int i = 0; i < 4; i++) {
                float v = h1v + sh2[(tg * 4 + i) * 64 + d];
                acc[i] += fast_tanh(v) * w;
            }
        }
    }

#pragma unroll
    for (int i = 0; i < 4; i++)
        g_scores[(long)(bz * 256 + t0 + tg * 4 + i) * 256 + e0 + e] = acc[i];
}

// ----------------------------- row softmax (in place) -----------------------
__global__ void __launch_bounds__(256) softmax_kernel()
{
    float* p = g_scores + (long)blockIdx.x * 256;
    const int tid = threadIdx.x;
    const int lane = tid & 31, w = tid >> 5;
    __shared__ float redm[8];
    __shared__ float reds[8];

    float v = p[tid];
    float m = v;
#pragma unroll
    for (int o = 16; o; o >>= 1) m = fmaxf(m, __shfl_xor_sync(0xffffffffu, m, o));
    if (lane == 0) redm[w] = m;
    __syncthreads();
    if (tid < 32) {
        float x = (tid < 8) ? redm[tid] : -1e30f;
#pragma unroll
        for (int o = 4; o; o >>= 1) x = fmaxf(x, __shfl_xor_sync(0xffffffffu, x, o));
        if (tid == 0) redm[0] = x;
    }
    __syncthreads();
    float ev = __expf(v - redm[0]);
    float ssum = ev;
#pragma unroll
    for (int o = 16; o; o >>= 1) ssum += __shfl_xor_sync(0xffffffffu, ssum, o);
    if (lane == 0) reds[w] = ssum;
    __syncthreads();
    if (tid < 32) {
        float x = (tid < 8) ? reds[tid] : 0.f;
#pragma unroll
        for (int o = 4; o; o >>= 1) x += __shfl_xor_sync(0xffffffffu, x, o);
        if (tid == 0) reds[0] = x;
    }
    __syncthreads();
    p[tid] = ev / reds[0];
}

// ----------------------------- launch ---------------------------------------
extern "C" void kernel_launch(void* const* d_in, const int* in_sizes, int n_in,
                              void* d_out, int out_size)
{
    const float* inputs   = (const float*)d_in[0];
    const float* attended = (const float*)d_in[1];
    const float* Wk       = (const float*)d_in[2];
    const float* Wr       = (const float*)d_in[3];
    const float* lstm_b   = (const float*)d_in[4];
    const float* W1       = (const float*)d_in[5];
    const float* b1       = (const float*)d_in[6];
    const float* W3       = (const float*)d_in[7];
    /* b3 (d_in[8]) cancels in softmax */
    const float* Wout     = (const float*)d_in[9];
    const float* bout     = (const float*)d_in[10];
    float* dout = (float*)d_out;

    static float* pXg = nullptr;
    static float* pH1 = nullptr;
    static float* pH2 = nullptr;
    static float* pXC = nullptr;
    static float* pSc = nullptr;
    static float* pPt = nullptr;
    static cudaStream_t s1 = nullptr;
    static cudaEvent_t evA = nullptr, evB = nullptr;
    static bool attr_done = false;
    if (!pXg) {
        cudaGetSymbolAddress((void**)&pXg, g_Xg);
        cudaGetSymbolAddress((void**)&pH1, g_h1);
        cudaGetSymbolAddress((void**)&pH2, g_h2);
        cudaGetSymbolAddress((void**)&pXC, g_XC);
        cudaGetSymbolAddress((void**)&pSc, g_scores);
        cudaGetSymbolAddress((void**)&pPt, g_part);
    }
    const int LSTM_SMEM = 14468 * 4;   // 57,872 B
    if (!attr_done) {
        cudaFuncSetAttribute(lstm_kernel, cudaFuncAttributeMaxDynamicSharedMemorySize,
                             LSTM_SMEM);
        cudaStreamCreateWithFlags(&s1, cudaStreamNonBlocking);
        cudaEventCreateWithFlags(&evA, cudaEventDisableTiming);
        cudaEventCreateWithFlags(&evB, cudaEventDisableTiming);
        attr_done = true;
    }
    const long PS = (long)ROWS * D;

    // fork side stream: h1 = attended @ W1 + b1 (independent of LSTM chain)
    cudaEventRecord(evA, 0);
    cudaStreamWaitEvent(s1, evA, 0);
    sgemm128<<<dim3(8, 16, 2), 256, 0, s1>>>(attended, D, 256, W1, D, 256L * D,
                                             pPt + 2 * PS, D, PS, ROWS, D, 256, nullptr);
    reduce_parts<<<PS / 1024, 256, 0, s1>>>(pPt + 2 * PS, PS, 2, b1, D, pH1, (int)PS);
    cudaEventRecord(evB, s1);

    // main stream: Xg -> LSTM(+h2 fold) -> (join h1) scores -> softmax -> weighted -> out
    sgemm128<<<dim3(32, 16, 1), 256>>>(inputs, DIN, 0, Wk, 4 * D, 0,
                                       pXg, 4 * D, 0, ROWS, 4 * D, DIN, lstm_b);
    lstm_kernel<<<NBLK_LSTM, 256, LSTM_SMEM>>>(Wr, W1, b1, dout);

    cudaStreamWaitEvent(0, evB, 0);   // join h1 before scores
    scores_kernel<<<dim3(4, 16, 8), 256>>>(W3);
    softmax_kernel<<<ROWS, 256>>>();
    sgemm128<<<dim3(8, 2, 8), 256>>>(pSc, TE, (long)TD * TE,
                                     attended, D, (long)TE * D,
                                     pXC + D, 2 * D, (long)TD * 2 * D,
                                     TD, D, TE, nullptr);
    {
        const long OS = (long)ROWS * MEL;
        sgemm128<<<dim3(2, 16, 4), 256>>>(pXC, 2 * D, 256, Wout, MEL, 256L * MEL,
                                          pPt, MEL, OS, ROWS, MEL, 256, nullptr);
        reduce_parts<<<(unsigned)(OS / 1024), 256>>>(pPt, OS, 4, bout, MEL, dout, (int)OS);
    }
}

// round 17
// speedup vs baseline: 1.4987x; 1.0105x over previous
#include <cuda_runtime.h>
#include <math.h>

#define BATCH 8
#define TD 256
#define TE 256
#define DIN 80
#define D 512
#define MEL 80
#define ROWS (BATCH*TD)          // 2048
#define NBLK_LSTM 128

// ----------------------------- scratch (device globals) ---------------------
__device__ __align__(16) float g_Xg[ROWS * 4 * D];        // inputs@Wk + b : [2048][2048]
__device__ __align__(16) float g_h1[ROWS * D];            // attended@W1+b1: [2048][512]
__device__ __align__(16) float g_h2[ROWS * D];            // x@W1+b1      : [2048][512]
__device__ __align__(16) float g_XC[ROWS * 2 * D];        // [x | weighted]: [2048][1024]
__device__ __align__(16) float g_scores[BATCH * TD * TE]; // scores/attn   : [2048][256]
__device__ __align__(16) float g_part[4 * ROWS * D];      // split-K partials
__device__ __align__(16) float g_hbuf[2][BATCH * D];      // double-buffered h
__device__ __align__(16) unsigned g_pfl[NBLK_LSTM];       // packed per-CTA flags (contiguous)

// ----------------------------- helpers --------------------------------------
__device__ __forceinline__ float fast_tanh(float x) {
    float y;
    asm("tanh.approx.f32 %0, %1;" : "=f"(y) : "f"(x));
    return y;
}
__device__ __forceinline__ unsigned ldg_relaxed_u32(const unsigned* p) {
    unsigned v;
    asm volatile("ld.relaxed.gpu.global.u32 %0, [%1];" : "=r"(v) : "l"(p) : "memory");
    return v;
}
__device__ __forceinline__ uint4 ldg_relaxed_u4(const uint4* p) {
    uint4 v;
    asm volatile("ld.relaxed.gpu.global.v4.u32 {%0,%1,%2,%3}, [%4];"
                 : "=r"(v.x), "=r"(v.y), "=r"(v.z), "=r"(v.w) : "l"(p) : "memory");
    return v;
}
__device__ __forceinline__ void stg_relaxed_u32(unsigned* p, unsigned v) {
    asm volatile("st.relaxed.gpu.global.u32 [%0], %1;" :: "l"(p), "r"(v) : "memory");
}
__device__ __forceinline__ void stg_release_u32(unsigned* p, unsigned v) {
    asm volatile("st.release.gpu.global.u32 [%0], %1;" :: "l"(p), "r"(v) : "memory");
}
__device__ __forceinline__ void stg_relaxed_f32(float* p, float v) {
    asm volatile("st.relaxed.gpu.global.f32 [%0], %1;" :: "l"(p), "f"(v) : "memory");
}
__device__ __forceinline__ float4 ldg_relaxed_f4(const float4* p) {
    float4 v;
    asm volatile("ld.relaxed.gpu.global.v4.f32 {%0,%1,%2,%3}, [%4];"
                 : "=f"(v.x), "=f"(v.y), "=f"(v.z), "=f"(v.w) : "l"(p) : "memory");
    return v;
}
__device__ __forceinline__ void fence_gpu() {
    asm volatile("fence.acq_rel.gpu;" ::: "memory");
}
__device__ __forceinline__ float sigm_e(float x) { return 1.f / (1.f + __expf(-x)); }
__device__ __forceinline__ float tanh_e(float x) { return 1.f - 2.f / (1.f + __expf(2.f * x)); }
#define DOT4(a,b) ((a).x*(b).x + (a).y*(b).y + (a).z*(b).z + (a).w*(b).w)

// ----------------------------- fast SGEMM: 128x64 tile, 8x4 micro -----------
__global__ void __launch_bounds__(256) sgemm128(
    const float* __restrict__ A, int lda, long sA,
    const float* __restrict__ B, int ldb, long sB,
    float* __restrict__ C, int ldc, long sC,
    int M, int N, int K, const float* __restrict__ bias)
{
    __shared__ float As[16][132];
    __shared__ float Bs[16][64];

    const int tid = threadIdx.x;
    const int tx = tid & 15;
    const int ty = tid >> 4;
    const int m0 = blockIdx.y << 7, n0 = blockIdx.x << 6;
    A += (long)blockIdx.z * sA;
    B += (long)blockIdx.z * sB;
    C += (long)blockIdx.z * sC;

    const int ar = tid >> 2, ac4 = (tid & 3) << 2;
    const int br = tid >> 4, bc4 = (tid & 15) << 2;

    float acc[8][4];
#pragma unroll
    for (int i = 0; i < 8; i++)
#pragma unroll
        for (int j = 0; j < 4; j++) acc[i][j] = 0.f;

    for (int k0 = 0; k0 < K; k0 += 16) {
#pragma unroll
        for (int h = 0; h < 2; h++) {
            int m = ar + (h << 6);
            float4 v = *(const float4*)&A[(long)(m0 + m) * lda + k0 + ac4];
            As[ac4 + 0][m] = v.x;
            As[ac4 + 1][m] = v.y;
            As[ac4 + 2][m] = v.z;
            As[ac4 + 3][m] = v.w;
        }
        float4 bv = make_float4(0.f, 0.f, 0.f, 0.f);
        if (n0 + bc4 + 3 < N) {
            bv = *(const float4*)&B[(long)(k0 + br) * ldb + n0 + bc4];
        } else {
            float* p = (float*)&bv;
#pragma unroll
            for (int c = 0; c < 4; c++)
                if (n0 + bc4 + c < N) p[c] = B[(long)(k0 + br) * ldb + n0 + bc4 + c];
        }
        *(float4*)&Bs[br][bc4] = bv;
        __syncthreads();

#pragma unroll
        for (int k = 0; k < 16; k++) {
            float4 a0 = *(const float4*)&As[k][ty * 8];
            float4 a1 = *(const float4*)&As[k][ty * 8 + 4];
            float4 b4 = *(const float4*)&Bs[k][tx * 4];
            acc[0][0] += a0.x * b4.x; acc[0][1] += a0.x * b4.y; acc[0][2] += a0.x * b4.z; acc[0][3] += a0.x * b4.w;
            acc[1][0] += a0.y * b4.x; acc[1][1] += a0.y * b4.y; acc[1][2] += a0.y * b4.z; acc[1][3] += a0.y * b4.w;
            acc[2][0] += a0.z * b4.x; acc[2][1] += a0.z * b4.y; acc[2][2] += a0.z * b4.z; acc[2][3] += a0.z * b4.w;
            acc[3][0] += a0.w * b4.x; acc[3][1] += a0.w * b4.y; acc[3][2] += a0.w * b4.z; acc[3][3] += a0.w * b4.w;
            acc[4][0] += a1.x * b4.x; acc[4][1] += a1.x * b4.y; acc[4][2] += a1.x * b4.z; acc[4][3] += a1.x * b4.w;
            acc[5][0] += a1.y * b4.x; acc[5][1] += a1.y * b4.y; acc[5][2] += a1.y * b4.z; acc[5][3] += a1.y * b4.w;
            acc[6][0] += a1.z * b4.x; acc[6][1] += a1.z * b4.y; acc[6][2] += a1.z * b4.z; acc[6][3] += a1.z * b4.w;
            acc[7][0] += a1.w * b4.x; acc[7][1] += a1.w * b4.y; acc[7][2] += a1.w * b4.z; acc[7][3] += a1.w * b4.w;
        }
        __syncthreads();
    }

#pragma unroll
    for (int i = 0; i < 8; i++) {
        int m = m0 + ty * 8 + i;
#pragma unroll
        for (int j = 0; j < 4; j++) {
            int n = n0 + tx * 4 + j;
            if (n < N) {
                float v = acc[i][j];
                if (bias) v += bias[n];
                C[(long)m * ldc + n] = v;
            }
        }
    }
}

// ----------------------------- split-K partial reduce ------------------------
__global__ void __launch_bounds__(256) reduce_parts(
    const float* __restrict__ parts, long pstride, int nparts,
    const float* __restrict__ bias, int bmod, float* __restrict__ out, int n)
{
    int i = (blockIdx.x * 256 + threadIdx.x) << 2;
    if (i >= n) return;
    float4 a = *(const float4*)&parts[i];
    for (int p = 1; p < nparts; p++) {
        float4 b = *(const float4*)&parts[(long)p * pstride + i];
        a.x += b.x; a.y += b.y; a.z += b.z; a.w += b.w;
    }
    int bi = i % bmod;
    a.x += bias[bi]; a.y += bias[bi + 1]; a.z += bias[bi + 2]; a.w += bias[bi + 3];
    *(float4*)&out[i] = a;
}

// ----------------------------- persistent LSTM + fused h2 -------------------
// R16 champion + release-store flag publish (replaces publish-side
// fence.acq_rel.gpu + relaxed store). Acquire side unchanged.
__global__ void __launch_bounds__(256) lstm_kernel(
    const float* __restrict__ Wr, const float* __restrict__ W1,
    const float* __restrict__ b1, float* __restrict__ dout)
{
    extern __shared__ float s[];
    float* sWr = s;                         // [16 cols][512 k]   8192 f
    float* sh = s + 8192;                   // [8 b][512 k]       4096 f
    float* szred = s + 12288;               // [8 b][16 c]         128 f
    float* sW1 = s + 12416;                 // [4 c][512 k]       2048 f
    float* sB1 = s + 14464;                 // [4]
    const float4* sWrv = (const float4*)sWr;
    float4* shv = (float4*)sh;
    const float4* sW1v = (const float4*)sW1;
    __shared__ unsigned s_base;

    const int tid = threadIdx.x;
    const int hu0 = blockIdx.x << 2;
    const int lane = tid & 31, warp = tid >> 5;
    const int cb = warp & 3, bb = warp >> 2;  // col-block (=gate), batch-block
    const int gb = tid >> 2, gu = tid & 3;    // gate-thread mapping (tid<32)
    // h2-fold warp set {1,2,3,5}: SMSPs 1,2,3,1 — never SMSP 0
    const bool h2w = (warp >= 1 && warp <= 3) || (warp == 5);
    const int hw = (warp == 5) ? 3 : (warp - 1);   // 0..3 -> batches {2hw, 2hw+1}

    // stage Wr slice: sWr[c*512+k] = Wr[k][512*gate + hu0 + u]
    for (int idx = tid; idx < 8192; idx += 256) {
        int c = idx >> 9, k = idx & 511;
        int col = ((c >> 2) << 9) + hu0 + (c & 3);
        sWr[idx] = Wr[k * 2048 + col];
    }
    // stage W1 slice: sW1[c*512+k] = W1[k][hu0 + c]
    for (int idx = tid; idx < 2048; idx += 256) {
        int c = idx >> 9, k = idx & 511;
        sW1[idx] = W1[k * 512 + hu0 + c];
    }
    if (tid < 4) sB1[tid] = b1[hu0 + tid];

    if (tid == 0) s_base = ldg_relaxed_u32(&g_pfl[blockIdx.x]);
    if (tid < 32) stg_relaxed_f32(&g_hbuf[0][gb * 512 + hu0 + gu], 0.f);   // h0 = 0
    __syncthreads();
    const unsigned base = s_base;
    if (tid == 0) stg_release_u32(&g_pfl[blockIdx.x], base + 1u);

    float creg = 0.f;

    for (int t = 0; t < TD; t++) {
        const int cur = t & 1, nxt = cur ^ 1;
        const unsigned tgt = base + (unsigned)t + 1u;

        // prefetch Xg for this step (overlaps the wait)
        float xg0 = 0.f, xg1 = 0.f, xg2 = 0.f, xg3 = 0.f;
        if (tid < 32) {
            const float* xr = &g_Xg[((gb << 8) + t) * 2048 + hu0 + gu];
            xg0 = xr[0]; xg1 = xr[512]; xg2 = xr[1024]; xg3 = xr[1536];
        }

        // vectorized all-poll-all barrier: lane l checks CTAs 4l..4l+3
        if (warp == 0) {
            const uint4* fp = (const uint4*)g_pfl;
            bool ok;
            do {
                uint4 f = ldg_relaxed_u4(&fp[lane]);
                ok = ((int)(f.x - tgt) >= 0) & ((int)(f.y - tgt) >= 0) &
                     ((int)(f.z - tgt) >= 0) & ((int)(f.w - tgt) >= 0);
            } while (!__all_sync(0xffffffffu, ok));
            fence_gpu();
        }
        __syncthreads();

        // stage h(t) = x[t-1] into SMEM
        const float4* src = (const float4*)g_hbuf[cur];
#pragma unroll
        for (int i = 0; i < 4; i++) shv[tid + (i << 8)] = ldg_relaxed_f4(&src[tid + (i << 8)]);
        __syncthreads();

        // GEMV: warp (cb,bb) computes z[bb*4..+3][cb*4..+3], k lane-vectorized
        float acc[4][4];
#pragma unroll
        for (int i = 0; i < 4; i++)
#pragma unroll
            for (int j = 0; j < 4; j++) acc[i][j] = 0.f;

#pragma unroll
        for (int kk = 0; kk < 4; kk++) {
            const int kv = (kk << 5) + lane;
            float4 h0 = shv[((bb << 2) + 0) * 128 + kv];
            float4 h1 = shv[((bb << 2) + 1) * 128 + kv];
            float4 h2 = shv[((bb << 2) + 2) * 128 + kv];
            float4 h3 = shv[((bb << 2) + 3) * 128 + kv];
            float4 w0 = sWrv[((cb << 2) + 0) * 128 + kv];
            float4 w1 = sWrv[((cb << 2) + 1) * 128 + kv];
            float4 w2 = sWrv[((cb << 2) + 2) * 128 + kv];
            float4 w3 = sWrv[((cb << 2) + 3) * 128 + kv];
            acc[0][0] += DOT4(h0, w0); acc[0][1] += DOT4(h0, w1); acc[0][2] += DOT4(h0, w2); acc[0][3] += DOT4(h0, w3);
            acc[1][0] += DOT4(h1, w0); acc[1][1] += DOT4(h1, w1); acc[1][2] += DOT4(h1, w2); acc[1][3] += DOT4(h1, w3);
            acc[2][0] += DOT4(h2, w0); acc[2][1] += DOT4(h2, w1); acc[2][2] += DOT4(h2, w2); acc[2][3] += DOT4(h2, w3);
            acc[3][0] += DOT4(h3, w0); acc[3][1] += DOT4(h3, w1); acc[3][2] += DOT4(h3, w2); acc[3][3] += DOT4(h3, w3);
        }

        // butterfly reduce over 32 k-lanes
#pragma unroll
        for (int off = 16; off; off >>= 1)
#pragma unroll
            for (int i = 0; i < 4; i++)
#pragma unroll
                for (int j = 0; j < 4; j++)
                    acc[i][j] += __shfl_xor_sync(0xffffffffu, acc[i][j], off);

        if (lane < 16) {
            int i = lane >> 2, j = lane & 3;
            szred[((bb << 2) + i) * 16 + ((cb << 2) + j)] = acc[i][j];
        }
        __syncthreads();

        // warp 0: gates (critical path, alone in SMSP 0). warps {1,2,3,5}: h2.
        if (tid < 32) {
            float zi = szred[gb * 16 + 0 + gu] + xg0;
            float zf = szred[gb * 16 + 4 + gu] + xg1;
            float zg = szred[gb * 16 + 8 + gu] + xg2;
            float zo = szred[gb * 16 + 12 + gu] + xg3;
            float ig = sigm_e(zi);
            float fg = sigm_e(zf);
            float gg = tanh_e(zg);
            float og = sigm_e(zo);
            creg = fg * creg + ig * gg;
            float h = og * tanh_e(creg);
            stg_relaxed_f32(&g_hbuf[nxt][gb * 512 + hu0 + gu], h);
            g_XC[((gb << 8) + t) * 1024 + hu0 + gu] = h;   // x sequence
            if (t == TD - 1) {
                dout[ROWS * MEL + gb * 512 + hu0 + gu] = h;                 // state_h
                dout[ROWS * MEL + BATCH * D + gb * 512 + hu0 + gu] = creg;  // state_c
            }
            __syncwarp();   // orders lanes' h stores before tid0's release
            if (tid == 0) stg_release_u32(&g_pfl[blockIdx.x], base + (unsigned)t + 2u);
        } else if (h2w && t > 0) {
            const int trow = t - 1;
            float a0c[4] = {0.f, 0.f, 0.f, 0.f};
            float a1c[4] = {0.f, 0.f, 0.f, 0.f};
#pragma unroll
            for (int j = 0; j < 4; j++) {
                const int k4 = (j << 5) + lane;
                float4 hA = shv[((hw << 1) + 0) * 128 + k4];
                float4 hB = shv[((hw << 1) + 1) * 128 + k4];
#pragma unroll
                for (int c = 0; c < 4; c++) {
                    float4 wv = sW1v[c * 128 + k4];
                    a0c[c] += DOT4(hA, wv);
                    a1c[c] += DOT4(hB, wv);
                }
            }
#pragma unroll
            for (int off = 16; off; off >>= 1)
#pragma unroll
                for (int c = 0; c < 4; c++) {
                    a0c[c] += __shfl_xor_sync(0xffffffffu, a0c[c], off);
                    a1c[c] += __shfl_xor_sync(0xffffffffu, a1c[c], off);
                }
#pragma unroll
            for (int c = 0; c < 4; c++) {
                if (lane == c)
                    g_h2[(((hw << 1) << 8) | trow) * 512 + hu0 + c] = a0c[c] + sB1[c];
                if (lane == 4 + c)
                    g_h2[((((hw << 1) + 1) << 8) | trow) * 512 + hu0 + c] = a1c[c] + sB1[c];
            }
        }
    }

    // tail: h2 row TD-1 needs x[TD-1] = h(256), which lives in g_hbuf[0]
    {
        const unsigned tgt = base + (unsigned)TD + 1u;
        if (warp == 0) {
            const uint4* fp = (const uint4*)g_pfl;
            bool ok;
            do {
                uint4 f = ldg_relaxed_u4(&fp[lane]);
                ok = ((int)(f.x - tgt) >= 0) & ((int)(f.y - tgt) >= 0) &
                     ((int)(f.z - tgt) >= 0) & ((int)(f.w - tgt) >= 0);
            } while (!__all_sync(0xffffffffu, ok));
            fence_gpu();
        }
        __syncthreads();
        const float4* src = (const float4*)g_hbuf[0];
#pragma unroll
        for (int i = 0; i < 4; i++) shv[tid + (i << 8)] = ldg_relaxed_f4(&src[tid + (i << 8)]);
        __syncthreads();
        if (h2w) {
            float a0c[4] = {0.f, 0.f, 0.f, 0.f};
            float a1c[4] = {0.f, 0.f, 0.f, 0.f};
#pragma unroll
            for (int j = 0; j < 4; j++) {
                const int k4 = (j << 5) + lane;
                float4 hA = shv[((hw << 1) + 0) * 128 + k4];
                float4 hB = shv[((hw << 1) + 1) * 128 + k4];
#pragma unroll
                for (int c = 0; c < 4; c++) {
                    float4 wv = sW1v[c * 128 + k4];
                    a0c[c] += DOT4(hA, wv);
                    a1c[c] += DOT4(hB, wv);
                }
            }
#pragma unroll
            for (int off = 16; off; off >>= 1)
#pragma unroll
                for (int c = 0; c < 4; c++) {
                    a0c[c] += __shfl_xor_sync(0xffffffffu, a0c[c], off);
                    a1c[c] += __shfl_xor_sync(0xffffffffu, a1c[c], off);
                }
#pragma unroll
            for (int c = 0; c < 4; c++) {
                if (lane == c)
                    g_h2[(((hw << 1) << 8) | (TD - 1)) * 512 + hu0 + c] = a0c[c] + sB1[c];
                if (lane == 4 + c)
                    g_h2[((((hw << 1) + 1) << 8) | (TD - 1)) * 512 + hu0 + c] = a1c[c] + sB1[c];
            }
        }
    }
}

// ----------------------------- attention scores -----------------------------
__global__ void __launch_bounds__(256) scores_kernel(const float* __restrict__ W3)
{
    __shared__ float sh1[64 * 65];
    __shared__ float sh2[16 * 64];
    __shared__ float sW3[512];

    const int tid = threadIdx.x;
    const int bz = blockIdx.z, t0 = blockIdx.y << 4, e0 = blockIdx.x << 6;
    const int e = tid & 63, tg = tid >> 6;

    sW3[tid] = W3[tid];
    sW3[tid + 256] = W3[tid + 256];

    float acc[4] = {0.f, 0.f, 0.f, 0.f};

    for (int dc = 0; dc < 512; dc += 64) {
        __syncthreads();
#pragma unroll
        for (int i = 0; i < 4; i++) {
            int q = tid + (i << 8);
            int er = q >> 4, d4 = (q & 15) << 2;
            float4 v = *(const float4*)&g_h1[(long)(bz * 256 + e0 + er) * 512 + dc + d4];
            sh1[(d4 + 0) * 65 + er] = v.x;
            sh1[(d4 + 1) * 65 + er] = v.y;
            sh1[(d4 + 2) * 65 + er] = v.z;
            sh1[(d4 + 3) * 65 + er] = v.w;
        }
        {
            int tt = tid >> 4, d4 = (tid & 15) << 2;
            float4 v = *(const float4*)&g_h2[(long)(bz * 256 + t0 + tt) * 512 + dc + d4];
            *(float4*)&sh2[tt * 64 + d4] = v;
        }
        __syncthreads();

#pragma unroll 8
        for (int d = 0; d < 64; d++) {
            float h1v = sh1[d * 65 + e];
            float w = sW3[dc + d];
#pragma unroll
            for (int i = 0; i < 4; i++) {
                float v = h1v + sh2[(tg * 4 + i) * 64 + d];
                acc[i] += fast_tanh(v) * w;
            }
        }
    }

#pragma unroll
    for (int i = 0; i < 4; i++)
        g_scores[(long)(bz * 256 + t0 + tg * 4 + i) * 256 + e0 + e] = acc[i];
}

// ----------------------------- row softmax (in place) -----------------------
__global__ void __launch_bounds__(256) softmax_kernel()
{
    float* p = g_scores + (long)blockIdx.x * 256;
    const int tid = threadIdx.x;
    const int lane = tid & 31, w = tid >> 5;
    __shared__ float redm[8];
    __shared__ float reds[8];

    float v = p[tid];
    float m = v;
#pragma unroll
    for (int o = 16; o; o >>= 1) m = fmaxf(m, __shfl_xor_sync(0xffffffffu, m, o));
    if (lane == 0) redm[w] = m;
    __syncthreads();
    if (tid < 32) {
        float x = (tid < 8) ? redm[tid] : -1e30f;
#pragma unroll
        for (int o = 4; o; o >>= 1) x = fmaxf(x, __shfl_xor_sync(0xffffffffu, x, o));
        if (tid == 0) redm[0] = x;
    }
    __syncthreads();
    float ev = __expf(v - redm[0]);
    float ssum = ev;
#pragma unroll
    for (int o = 16; o; o >>= 1) ssum += __shfl_xor_sync(0xffffffffu, ssum, o);
    if (lane == 0) reds[w] = ssum;
    __syncthreads();
    if (tid < 32) {
        float x = (tid < 8) ? reds[tid] : 0.f;
#pragma unroll
        for (int o = 4; o; o >>= 1) x += __shfl_xor_sync(0xffffffffu, x, o);
        if (tid == 0) reds[0] = x;
    }
    __syncthreads();
    p[tid] = ev / reds[0];
}

// ----------------------------- launch ---------------------------------------
extern "C" void kernel_launch(void* const* d_in, const int* in_sizes, int n_in,
                              void* d_out, int out_size)
{
    const float* inputs   = (const float*)d_in[0];
    const float* attended = (const float*)d_in[1];
    const float* Wk       = (const float*)d_in[2];
    const float* Wr       = (const float*)d_in[3];
    const float* lstm_b   = (const float*)d_in[4];
    const float* W1       = (const float*)d_in[5];
    const float* b1       = (const float*)d_in[6];
    const float* W3       = (const float*)d_in[7];
    /* b3 (d_in[8]) cancels in softmax */
    const float* Wout     = (const float*)d_in[9];
    const float* bout     = (const float*)d_in[10];
    float* dout = (float*)d_out;

    static float* pXg = nullptr;
    static float* pH1 = nullptr;
    static float* pH2 = nullptr;
    static float* pXC = nullptr;
    static float* pSc = nullptr;
    static float* pPt = nullptr;
    static cudaStream_t s1 = nullptr;
    static cudaEvent_t evA = nullptr, evB = nullptr;
    static bool attr_done = false;
    if (!pXg) {
        cudaGetSymbolAddress((void**)&pXg, g_Xg);
        cudaGetSymbolAddress((void**)&pH1, g_h1);
        cudaGetSymbolAddress((void**)&pH2, g_h2);
        cudaGetSymbolAddress((void**)&pXC, g_XC);
        cudaGetSymbolAddress((void**)&pSc, g_scores);
        cudaGetSymbolAddress((void**)&pPt, g_part);
    }
    const int LSTM_SMEM = 14468 * 4;   // 57,872 B
    if (!attr_done) {
        cudaFuncSetAttribute(lstm_kernel, cudaFuncAttributeMaxDynamicSharedMemorySize,
                             LSTM_SMEM);
        cudaStreamCreateWithFlags(&s1, cudaStreamNonBlocking);
        cudaEventCreateWithFlags(&evA, cudaEventDisableTiming);
        cudaEventCreateWithFlags(&evB, cudaEventDisableTiming);
        attr_done = true;
    }
    const long PS = (long)ROWS * D;

    // fork side stream: h1 = attended @ W1 + b1 (independent of LSTM chain)
    cudaEventRecord(evA, 0);
    cudaStreamWaitEvent(s1, evA, 0);
    sgemm128<<<dim3(8, 16, 2), 256, 0, s1>>>(attended, D, 256, W1, D, 256L * D,
                                             pPt + 2 * PS, D, PS, ROWS, D, 256, nullptr);
    reduce_parts<<<PS / 1024, 256, 0, s1>>>(pPt + 2 * PS, PS, 2, b1, D, pH1, (int)PS);
    cudaEventRecord(evB, s1);

    // main stream: Xg -> LSTM(+h2 fold) -> (join h1) scores -> softmax -> weighted -> out
    sgemm128<<<dim3(32, 16, 1), 256>>>(inputs, DIN, 0, Wk, 4 * D, 0,
                                       pXg, 4 * D, 0, ROWS, 4 * D, DIN, lstm_b);
    lstm_kernel<<<NBLK_LSTM, 256, LSTM_SMEM>>>(Wr, W1, b1, dout);

    cudaStreamWaitEvent(0, evB, 0);   // join h1 before scores
    scores_kernel<<<dim3(4, 16, 8), 256>>>(W3);
    softmax_kernel<<<ROWS, 256>>>();
    sgemm128<<<dim3(8, 2, 8), 256>>>(pSc, TE, (long)TD * TE,
                                     attended, D, (long)TE * D,
                                     pXC + D, 2 * D, (long)TD * 2 * D,
                                     TD, D, TE, nullptr);
    {
        const long OS = (long)ROWS * MEL;
        sgemm128<<<dim3(2, 16, 4), 256>>>(pXC, 2 * D, 256, Wout, MEL, 256L * MEL,
                                          pPt, MEL, OS, ROWS, MEL, 256, nullptr);
        reduce_parts<<<(unsigned)(OS / 1024), 256>>>(pPt, OS, 4, bout, MEL, dout, (int)OS);
    }
}